// round 14
// baseline (speedup 1.0000x reference)
#include <cuda_runtime.h>
#include <cuda_fp16.h>
#include <math.h>
#include <string.h>

#define NV 200000
#define NC 100000
#define NE 1200000
#define VFEAT 7
#define CFEAT 5
#define HDIM 64
#define NROUNDS 2
#define SCAN_TILE 2048
#define NBC_ ((NC + SCAN_TILE - 1) / SCAN_TILE)   // 49
#define NBV_ ((NV + SCAN_TILE - 1) / SCAN_TILE)   // 98
#define GPAD 68
#define XPAD 136

typedef unsigned long long ull;

// ---------------- fast helpers ----------------
__device__ __forceinline__ float fast_tanh(float x) {
    float y;
    asm("tanh.approx.f32 %0, %1;" : "=f"(y) : "f"(x));
    return y;
}
__device__ __forceinline__ ull bcast2(float x) {
    ull r;
    unsigned u = __float_as_uint(x);
    asm("mov.b64 %0, {%1, %1};" : "=l"(r) : "r"(u));
    return r;
}
__device__ __forceinline__ void ffma2(ull& d, ull a, ull b) {
    asm("fma.rn.f32x2 %0, %1, %2, %0;" : "+l"(d) : "l"(a), "l"(b));
}
__device__ __forceinline__ float2 unpack2(ull v) {
    float2 f;
    memcpy(&f, &v, 8);
    return f;
}
__device__ __forceinline__ unsigned packh2(float a, float b) {
    __half2 h = __floats2half2_rn(a, b);
    unsigned u;
    memcpy(&u, &h, 4);
    return u;
}
__device__ __forceinline__ float4 cvt_h4(uint2 u) {
    __half2 h0, h1;
    memcpy(&h0, &u.x, 4);
    memcpy(&h1, &u.y, 4);
    float2 a = __half22float2(h0);
    float2 b = __half22float2(h1);
    return make_float4(a.x, a.y, b.x, b.y);
}

// ---------------- device scratch ----------------
__device__ float  g_hvar[NV * HDIM];
__device__ float  g_hcon[NC * HDIM];
__device__ float  g_t[NV * HDIM];        // fp32 agg buffer (con side)
__device__ __half g_hvar16[NV * HDIM];   // fp16 mirror of hvar (con side gathers)
__device__ __half g_t16[NC * HDIM];      // fp16 messages (var side gathers)
__device__ int   g_deg_var[NV];
__device__ int   g_deg_con[NC];
__device__ int   g_row_var[NV + 1];
__device__ int   g_row_con[NC + 1];
__device__ int   g_adj_var[NE];
__device__ int   g_adj_con[NE];
__device__ int   g_bsum_var[128];
__device__ int   g_bsum_con[64];

// ---------------- zero one deg array ----------------
__global__ void k_zero1(int* __restrict__ deg, int n) {
    int i = blockIdx.x * blockDim.x + threadIdx.x;
    if (i < n) deg[i] = 0;
}

// ---------------- per-side histogram ----------------
__global__ void k_hist1(const int* __restrict__ idx, int* __restrict__ deg) {
    int e = blockIdx.x * blockDim.x + threadIdx.x;
    if (e < NE) atomicAdd(&deg[idx[e]], 1);
}

// ---------------- scan phase A ----------------
__global__ void k_scan_a(const int* __restrict__ deg, int n, int* __restrict__ bsum) {
    __shared__ int ws[8];
    int idx0 = blockIdx.x * SCAN_TILE + threadIdx.x * 8;
    int local = 0;
    #pragma unroll
    for (int i = 0; i < 8; i++) {
        int id = idx0 + i;
        if (id < n) local += deg[id];
    }
    int lane = threadIdx.x & 31, w = threadIdx.x >> 5;
    #pragma unroll
    for (int o = 16; o; o >>= 1) local += __shfl_xor_sync(0xffffffffu, local, o);
    if (lane == 0) ws[w] = local;
    __syncthreads();
    if (threadIdx.x == 0) {
        int s = 0;
        #pragma unroll
        for (int i = 0; i < 8; i++) s += ws[i];
        bsum[blockIdx.x] = s;
    }
}

// ---------------- scan phase B ----------------
__global__ void k_scan_b(int* bsum, int nb) {
    __shared__ int ws[4];
    int tid = threadIdx.x;
    int v = (tid < nb) ? bsum[tid] : 0;
    int lane = tid & 31, w = tid >> 5;
    int inc = v;
    #pragma unroll
    for (int o = 1; o < 32; o <<= 1) {
        int y = __shfl_up_sync(0xffffffffu, inc, o);
        if (lane >= o) inc += y;
    }
    if (lane == 31) ws[w] = inc;
    __syncthreads();
    int add = 0;
    for (int i = 0; i < w; i++) add += ws[i];
    if (tid < nb) bsum[tid] = inc - v + add;
}

// ---------------- scan phase C ----------------
__global__ void k_scan_c(const int* __restrict__ deg, int* __restrict__ row,
                         const int* __restrict__ bsum, int n) {
    __shared__ int wsum[8];
    int idx0 = blockIdx.x * SCAN_TILE + threadIdx.x * 8;
    int pre[8];
    int local = 0;
    #pragma unroll
    for (int i = 0; i < 8; i++) {
        int id = idx0 + i;
        int x = (id < n) ? deg[id] : 0;
        pre[i] = local;
        local += x;
    }
    int lane = threadIdx.x & 31, w = threadIdx.x >> 5;
    int inc = local;
    #pragma unroll
    for (int o = 1; o < 32; o <<= 1) {
        int y = __shfl_up_sync(0xffffffffu, inc, o);
        if (lane >= o) inc += y;
    }
    if (lane == 31) wsum[w] = inc;
    __syncthreads();
    int add = 0;
    for (int i = 0; i < w; i++) add += wsum[i];
    int texcl = bsum[blockIdx.x] + add + (inc - local);
    #pragma unroll
    for (int i = 0; i < 8; i++) {
        int id = idx0 + i;
        if (id < n) row[id] = texcl + pre[i];
    }
    if (blockIdx.x == 0 && threadIdx.x == 0) row[n] = NE;
}

// ---------------- per-side CSR fill (consumes deg via atomicSub) ----------------
__global__ void k_fill1(const int* __restrict__ key, const int* __restrict__ val,
                        const int* __restrict__ rowp, int* __restrict__ deg,
                        int* __restrict__ adj) {
    int e = blockIdx.x * blockDim.x + threadIdx.x;
    if (e < NE) {
        int k = key[e];
        int p = rowp[k] + (atomicSub(&deg[k], 1) - 1);
        adj[p] = val[e];
    }
}

// ---------------- 8x8-tile 64x64 GEMM core ----------------
__device__ __forceinline__ void gemm64_8x8(
    const float* Wt, const float* Xt, int j0, int n0, ull acc[8][4]) {
    #pragma unroll
    for (int a = 0; a < 8; a++) { acc[a][0] = 0ull; acc[a][1] = 0ull; acc[a][2] = 0ull; acc[a][3] = 0ull; }
    #pragma unroll 8
    for (int k = 0; k < 64; k++) {
        const float* wr = Wt + k * GPAD + j0;
        ulonglong2 wa = *(const ulonglong2*)wr;
        ulonglong2 wb = *(const ulonglong2*)(wr + 4);
        const float* xr = Xt + k * XPAD + n0;
        float4 xa = *(const float4*)xr;
        float4 xb = *(const float4*)(xr + 4);
        float xs[8] = {xa.x, xa.y, xa.z, xa.w, xb.x, xb.y, xb.z, xb.w};
        #pragma unroll
        for (int ni = 0; ni < 8; ni++) {
            ull xp = bcast2(xs[ni]);
            ffma2(acc[ni][0], xp, wa.x);
            ffma2(acc[ni][1], xp, wa.y);
            ffma2(acc[ni][2], xp, wb.x);
            ffma2(acc[ni][3], xp, wb.y);
        }
    }
}

// ---------------- fused encoder (optionally emits fp16 mirror) ----------------
template <int F, bool H16>
__global__ __launch_bounds__(128) void k_enc(
    const float* __restrict__ x, const float* __restrict__ W1,
    const float* __restrict__ b1, const float* __restrict__ W2,
    const float* __restrict__ b2, float* __restrict__ out,
    __half* __restrict__ out16, int n) {
    extern __shared__ float sm[];
    float* W1s = sm;
    float* b1s = sm + 64 * F;
    float* W2t = sm + 64 * F + 64;
    float* Xt  = sm + 64 * F + 64 + 64 * GPAD;
    int tid = threadIdx.x;
    int row0 = blockIdx.x * 128;
    for (int i = tid; i < 64 * F; i += 128) W1s[i] = W1[i];
    if (tid < 64) b1s[tid] = b1[tid];
    #pragma unroll
    for (int i = tid; i < 4096; i += 128) {
        int j = i >> 6, k = i & 63;
        W2t[k * GPAD + j] = W2[i];
    }
    float xf[F];
    {
        int row = row0 + tid;
        if (row < n) {
            #pragma unroll
            for (int f = 0; f < F; f++) xf[f] = x[(size_t)row * F + f];
        } else {
            #pragma unroll
            for (int f = 0; f < F; f++) xf[f] = 0.f;
        }
    }
    __syncthreads();
    {
        int row = row0 + tid;
        if (row < n) {
            #pragma unroll 4
            for (int k = 0; k < 64; k++) {
                float a = b1s[k];
                #pragma unroll
                for (int f = 0; f < F; f++) a += xf[f] * W1s[k * F + f];
                Xt[k * XPAD + tid] = fast_tanh(a);
            }
        } else {
            #pragma unroll 8
            for (int k = 0; k < 64; k++) Xt[k * XPAD + tid] = 0.f;
        }
    }
    __syncthreads();
    const int j0 = (tid & 7) * 8;
    const int n0 = (tid >> 3) * 8;
    ull acc[8][4];
    gemm64_8x8(W2t, Xt, j0, n0, acc);
    float4 ba = *(const float4*)&b2[j0];
    float4 bb = *(const float4*)&b2[j0 + 4];
    #pragma unroll
    for (int ni = 0; ni < 8; ni++) {
        int row = row0 + n0 + ni;
        if (row >= n) break;
        float2 p0 = unpack2(acc[ni][0]), p1 = unpack2(acc[ni][1]);
        float2 p2 = unpack2(acc[ni][2]), p3 = unpack2(acc[ni][3]);
        float v0 = p0.x + ba.x, v1 = p0.y + ba.y, v2 = p1.x + ba.z, v3 = p1.y + ba.w;
        float v4 = p2.x + bb.x, v5 = p2.y + bb.y, v6 = p3.x + bb.z, v7 = p3.y + bb.w;
        *(float4*)&out[(size_t)row * 64 + j0]     = make_float4(v0, v1, v2, v3);
        *(float4*)&out[(size_t)row * 64 + j0 + 4] = make_float4(v4, v5, v6, v7);
        if (H16) {
            uint4 hv;
            hv.x = packh2(v0, v1); hv.y = packh2(v2, v3);
            hv.z = packh2(v4, v5); hv.w = packh2(v6, v7);
            *(uint4*)&out16[(size_t)row * 64 + j0] = hv;
        }
    }
}

// ---------------- fused round GEMM pair (deg from rowp; fp16 message output) ----------------
__global__ __launch_bounds__(128) void k_gemm_pair(
    const float* __restrict__ agg, const float* __restrict__ W1,
    const float* __restrict__ b1, const int* __restrict__ rowp,
    float* hcon, const float* __restrict__ W2, __half* __restrict__ tout16, int n) {
    extern __shared__ float sm[];
    float* W1t  = sm;
    float* W2t  = sm + 64 * GPAD;
    float* Xt   = sm + 2 * 64 * GPAD;
    float* degs = sm + 2 * 64 * GPAD + 64 * XPAD;
    int tid = threadIdx.x;
    int row0 = blockIdx.x * 128;
    #pragma unroll
    for (int i = tid; i < 4096; i += 128) {
        int j = i >> 6, k = i & 63;
        W1t[k * GPAD + j] = W1[i];
        W2t[k * GPAD + j] = W2[i];
    }
    {
        int r = tid, row = row0 + r;
        if (row < n) {
            const float4* s4 = (const float4*)(agg + (size_t)row * 64);
            #pragma unroll
            for (int kk = 0; kk < 16; kk++) {
                float4 v = s4[kk];
                Xt[(kk * 4 + 0) * XPAD + r] = v.x;
                Xt[(kk * 4 + 1) * XPAD + r] = v.y;
                Xt[(kk * 4 + 2) * XPAD + r] = v.z;
                Xt[(kk * 4 + 3) * XPAD + r] = v.w;
            }
            degs[r] = (float)(rowp[row + 1] - rowp[row]);
        } else {
            #pragma unroll 8
            for (int k = 0; k < 64; k++) Xt[k * XPAD + r] = 0.f;
            degs[r] = 0.f;
        }
    }
    __syncthreads();
    const int j0 = (tid & 7) * 8;
    const int n0 = (tid >> 3) * 8;
    ull acc[8][4];
    gemm64_8x8(W1t, Xt, j0, n0, acc);
    __syncthreads();
    float4 ba = *(const float4*)&b1[j0];
    float4 bb = *(const float4*)&b1[j0 + 4];
    #pragma unroll
    for (int ni = 0; ni < 8; ni++) {
        int row = row0 + n0 + ni;
        float h[8];
        float2 p0 = unpack2(acc[ni][0]), p1 = unpack2(acc[ni][1]);
        float2 p2 = unpack2(acc[ni][2]), p3 = unpack2(acc[ni][3]);
        h[0] = p0.x; h[1] = p0.y; h[2] = p1.x; h[3] = p1.y;
        h[4] = p2.x; h[5] = p2.y; h[6] = p3.x; h[7] = p3.y;
        if (row < n) {
            float s = degs[n0 + ni];
            float4 r0 = *(const float4*)&hcon[(size_t)row * 64 + j0];
            float4 r1 = *(const float4*)&hcon[(size_t)row * 64 + j0 + 4];
            h[0] = fast_tanh(h[0] + ba.x * s + r0.x);
            h[1] = fast_tanh(h[1] + ba.y * s + r0.y);
            h[2] = fast_tanh(h[2] + ba.z * s + r0.z);
            h[3] = fast_tanh(h[3] + ba.w * s + r0.w);
            h[4] = fast_tanh(h[4] + bb.x * s + r1.x);
            h[5] = fast_tanh(h[5] + bb.y * s + r1.y);
            h[6] = fast_tanh(h[6] + bb.z * s + r1.z);
            h[7] = fast_tanh(h[7] + bb.w * s + r1.w);
            *(float4*)&hcon[(size_t)row * 64 + j0]     = make_float4(h[0], h[1], h[2], h[3]);
            *(float4*)&hcon[(size_t)row * 64 + j0 + 4] = make_float4(h[4], h[5], h[6], h[7]);
        } else {
            #pragma unroll
            for (int jj = 0; jj < 8; jj++) h[jj] = 0.f;
        }
        #pragma unroll
        for (int jj = 0; jj < 8; jj++) Xt[(j0 + jj) * XPAD + n0 + ni] = h[jj];
    }
    __syncthreads();
    gemm64_8x8(W2t, Xt, j0, n0, acc);
    #pragma unroll
    for (int ni = 0; ni < 8; ni++) {
        int row = row0 + n0 + ni;
        if (row >= n) break;
        float2 p0 = unpack2(acc[ni][0]), p1 = unpack2(acc[ni][1]);
        float2 p2 = unpack2(acc[ni][2]), p3 = unpack2(acc[ni][3]);
        uint4 v;
        v.x = packh2(p0.x, p0.y);
        v.y = packh2(p1.x, p1.y);
        v.z = packh2(p2.x, p2.y);
        v.w = packh2(p3.x, p3.y);
        *(uint4*)&tout16[(size_t)row * 64 + j0] = v;
    }
}

// ---------------- half-warp-per-row gather core (fp16 src, fp32 accum) ----------------
__device__ __forceinline__ float4 gather_row_hw_h(
    const __half* __restrict__ src, const int* __restrict__ adj,
    int b, int e, int fl) {
    float4 a0 = make_float4(0.f, 0.f, 0.f, 0.f);
    float4 a1 = a0, a2 = a0, a3 = a0;
    int i = b;
    for (; i + 4 <= e; i += 4) {
        int v0 = adj[i], v1 = adj[i + 1], v2 = adj[i + 2], v3 = adj[i + 3];
        uint2 u0 = *(const uint2*)&src[(size_t)v0 * 64 + fl * 4];
        uint2 u1 = *(const uint2*)&src[(size_t)v1 * 64 + fl * 4];
        uint2 u2 = *(const uint2*)&src[(size_t)v2 * 64 + fl * 4];
        uint2 u3 = *(const uint2*)&src[(size_t)v3 * 64 + fl * 4];
        float4 x0 = cvt_h4(u0), x1 = cvt_h4(u1), x2 = cvt_h4(u2), x3 = cvt_h4(u3);
        a0.x += x0.x; a0.y += x0.y; a0.z += x0.z; a0.w += x0.w;
        a1.x += x1.x; a1.y += x1.y; a1.z += x1.z; a1.w += x1.w;
        a2.x += x2.x; a2.y += x2.y; a2.z += x2.z; a2.w += x2.w;
        a3.x += x3.x; a3.y += x3.y; a3.z += x3.z; a3.w += x3.w;
    }
    for (; i < e; i++) {
        int v = adj[i];
        uint2 u = *(const uint2*)&src[(size_t)v * 64 + fl * 4];
        float4 x = cvt_h4(u);
        a0.x += x.x; a0.y += x.y; a0.z += x.z; a0.w += x.w;
    }
    a0.x = (a0.x + a1.x) + (a2.x + a3.x);
    a0.y = (a0.y + a1.y) + (a2.y + a3.y);
    a0.z = (a0.z + a1.z) + (a2.z + a3.z);
    a0.w = (a0.w + a1.w) + (a2.w + a3.w);
    return a0;
}

// ---------------- gather aggregation (2 rows per warp, fp16 src -> fp32 out) ----------------
__global__ __launch_bounds__(256) void k_agg(
    const __half* __restrict__ src16, const int* __restrict__ rowp,
    const int* __restrict__ adj, float* __restrict__ out, int n) {
    int gw = (blockIdx.x * 256 + threadIdx.x) >> 5;
    int lane = threadIdx.x & 31;
    int half = lane >> 4, fl = lane & 15;
    int row = gw * 2 + half;
    if (gw * 2 >= n) return;
    int b = rowp[row], e = rowp[row + 1];
    float4 a = gather_row_hw_h(src16, adj, b, e, fl);
    *(float4*)&out[(size_t)row * 64 + fl * 4] = a;
}

// ---------------- gather + update (fp16 src; writes fp32 h and fp16 mirror) ----------------
__global__ __launch_bounds__(256) void k_agg_update(
    const __half* __restrict__ src16, const int* __restrict__ rowp,
    const int* __restrict__ adj, float* h, __half* __restrict__ h16,
    const float* __restrict__ bias, int n) {
    int gw = (blockIdx.x * 256 + threadIdx.x) >> 5;
    int lane = threadIdx.x & 31;
    int half = lane >> 4, fl = lane & 15;
    int row = gw * 2 + half;
    if (gw * 2 >= n) return;
    int b = rowp[row], e = rowp[row + 1];
    float4 a = gather_row_hw_h(src16, adj, b, e, fl);
    float d = (float)(e - b);
    float4 bb = *(const float4*)&bias[fl * 4];
    float4 hv = *(const float4*)&h[(size_t)row * 64 + fl * 4];
    hv.x = fast_tanh(hv.x + a.x + d * bb.x);
    hv.y = fast_tanh(hv.y + a.y + d * bb.y);
    hv.z = fast_tanh(hv.z + a.z + d * bb.z);
    hv.w = fast_tanh(hv.w + a.w + d * bb.w);
    *(float4*)&h[(size_t)row * 64 + fl * 4] = hv;
    uint2 hp;
    hp.x = packh2(hv.x, hv.y);
    hp.y = packh2(hv.z, hv.w);
    *(uint2*)&h16[(size_t)row * 64 + fl * 4] = hp;
}

// ---------------- final: gather + update + readout (fp16 src) ----------------
__global__ __launch_bounds__(256) void k_agg_update_ro(
    const __half* __restrict__ src16, const int* __restrict__ rowp,
    const int* __restrict__ adj, const float* __restrict__ h,
    const float* __restrict__ bias, const float* __restrict__ Wro,
    const float* __restrict__ bro, float* __restrict__ scores, int n) {
    int gw = (blockIdx.x * 256 + threadIdx.x) >> 5;
    int lane = threadIdx.x & 31;
    int half = lane >> 4, fl = lane & 15;
    int row = gw * 2 + half;
    if (gw * 2 >= n) return;
    int b = rowp[row], e = rowp[row + 1];
    float4 a = gather_row_hw_h(src16, adj, b, e, fl);
    float d = (float)(e - b);
    float4 bb = *(const float4*)&bias[fl * 4];
    float4 hv = *(const float4*)&h[(size_t)row * 64 + fl * 4];
    float4 ww = *(const float4*)&Wro[fl * 4];
    float hx = fast_tanh(hv.x + a.x + d * bb.x);
    float hy = fast_tanh(hv.y + a.y + d * bb.y);
    float hz = fast_tanh(hv.z + a.z + d * bb.z);
    float hw = fast_tanh(hv.w + a.w + d * bb.w);
    float s = hx * ww.x + hy * ww.y + hz * ww.z + hw * ww.w;
    #pragma unroll
    for (int o = 8; o; o >>= 1) s += __shfl_xor_sync(0xffffffffu, s, o);
    if (fl == 0) scores[row] = s + bro[0];
}

// ---------------- launch ----------------
extern "C" void kernel_launch(void* const* d_in, const int* in_sizes, int n_in,
                              void* d_out, int out_size) {
    const float* var_features = (const float*)d_in[0];
    const float* con_features = (const float*)d_in[1];
    const int*   edge_var     = (const int*)d_in[2];
    const int*   edge_con     = (const int*)d_in[3];
    const float* W_ve1 = (const float*)d_in[4];
    const float* b_ve1 = (const float*)d_in[5];
    const float* W_ve2 = (const float*)d_in[6];
    const float* b_ve2 = (const float*)d_in[7];
    const float* W_ce1 = (const float*)d_in[8];
    const float* b_ce1 = (const float*)d_in[9];
    const float* W_ce2 = (const float*)d_in[10];
    const float* b_ce2 = (const float*)d_in[11];
    const float* W_v2c = (const float*)d_in[12];
    const float* b_v2c = (const float*)d_in[13];
    const float* W_c2v = (const float*)d_in[14];
    const float* b_c2v = (const float*)d_in[15];
    const float* W_ro  = (const float*)d_in[16];
    const float* b_ro  = (const float*)d_in[17];
    float* scores = (float*)d_out;

    float *hvar, *hcon, *tbuf;
    __half *hvar16, *t16;
    int *row_var, *row_con, *adj_var, *adj_con, *deg_var, *deg_con, *bsv, *bsc;
    cudaGetSymbolAddress((void**)&hvar, g_hvar);
    cudaGetSymbolAddress((void**)&hcon, g_hcon);
    cudaGetSymbolAddress((void**)&tbuf, g_t);
    cudaGetSymbolAddress((void**)&hvar16, g_hvar16);
    cudaGetSymbolAddress((void**)&t16, g_t16);
    cudaGetSymbolAddress((void**)&row_var, g_row_var);
    cudaGetSymbolAddress((void**)&row_con, g_row_con);
    cudaGetSymbolAddress((void**)&adj_var, g_adj_var);
    cudaGetSymbolAddress((void**)&adj_con, g_adj_con);
    cudaGetSymbolAddress((void**)&deg_var, g_deg_var);
    cudaGetSymbolAddress((void**)&deg_con, g_deg_con);
    cudaGetSymbolAddress((void**)&bsv, g_bsum_var);
    cudaGetSymbolAddress((void**)&bsc, g_bsum_con);

    const int GEMM_SMEM = (2 * 64 * GPAD + 64 * XPAD + 128) * sizeof(float);
    const int ENCV_SMEM = (64 * VFEAT + 64 + 64 * GPAD + 64 * XPAD) * sizeof(float);
    const int ENCC_SMEM = (64 * CFEAT + 64 + 64 * GPAD + 64 * XPAD) * sizeof(float);
    cudaFuncSetAttribute((const void*)k_gemm_pair, cudaFuncAttributeMaxDynamicSharedMemorySize, GEMM_SMEM);
    cudaFuncSetAttribute((const void*)k_enc<VFEAT, true>, cudaFuncAttributeMaxDynamicSharedMemorySize, ENCV_SMEM);
    cudaFuncSetAttribute((const void*)k_enc<CFEAT, false>, cudaFuncAttributeMaxDynamicSharedMemorySize, ENCC_SMEM);

    // ---- single side stream ----
    cudaStream_t s2;
    cudaStreamCreateWithFlags(&s2, cudaStreamNonBlocking);
    cudaEvent_t evFork, evEnc, evVar;
    cudaEventCreateWithFlags(&evFork, cudaEventDisableTiming);
    cudaEventCreateWithFlags(&evEnc, cudaEventDisableTiming);
    cudaEventCreateWithFlags(&evVar, cudaEventDisableTiming);
    cudaEventRecord(evFork, 0);
    cudaStreamWaitEvent(s2, evFork, 0);

    // s2: encoders, then var-side CSR chain
    k_enc<VFEAT, true><<<(NV + 127) / 128, 128, ENCV_SMEM, s2>>>(var_features, W_ve1, b_ve1, W_ve2, b_ve2, hvar, hvar16, NV);
    k_enc<CFEAT, false><<<(NC + 127) / 128, 128, ENCC_SMEM, s2>>>(con_features, W_ce1, b_ce1, W_ce2, b_ce2, hcon, nullptr, NC);
    cudaEventRecord(evEnc, s2);
    k_zero1<<<(NV + 255) / 256, 256, 0, s2>>>(deg_var, NV);
    k_hist1<<<(NE + 255) / 256, 256, 0, s2>>>(edge_var, deg_var);
    k_scan_a<<<NBV_, 256, 0, s2>>>(deg_var, NV, bsv);
    k_scan_b<<<1, 128, 0, s2>>>(bsv, NBV_);
    k_scan_c<<<NBV_, 256, 0, s2>>>(deg_var, row_var, bsv, NV);
    k_fill1<<<(NE + 255) / 256, 256, 0, s2>>>(edge_var, edge_con, row_var, deg_var, adj_var);
    cudaEventRecord(evVar, s2);

    // main: con-side CSR chain
    k_zero1<<<(NC + 255) / 256, 256>>>(deg_con, NC);
    k_hist1<<<(NE + 255) / 256, 256>>>(edge_con, deg_con);
    k_scan_a<<<NBC_, 256>>>(deg_con, NC, bsc);
    k_scan_b<<<1, 128>>>(bsc, NBC_);
    k_scan_c<<<NBC_, 256>>>(deg_con, row_con, bsc, NC);
    k_fill1<<<(NE + 255) / 256, 256>>>(edge_con, edge_var, row_con, deg_con, adj_con);

    // join encoders before round loop
    cudaStreamWaitEvent(0, evEnc, 0);

    // ---- message passing rounds ----
    for (int r = 0; r < NROUNDS; r++) {
        k_agg<<<(NC * 16 + 255) / 256, 256>>>(hvar16, row_con, adj_con, tbuf, NC);
        k_gemm_pair<<<(NC + 127) / 128, 128, GEMM_SMEM>>>(tbuf, W_v2c + r * 4096, b_v2c + r * 64,
                                                          row_con, hcon, W_c2v + r * 4096, t16, NC);
        if (r == 0) cudaStreamWaitEvent(0, evVar, 0);   // late join of var CSR chain
        if (r < NROUNDS - 1) {
            k_agg_update<<<(NV * 16 + 255) / 256, 256>>>(t16, row_var, adj_var, hvar, hvar16,
                                                         b_c2v + r * 64, NV);
        } else {
            k_agg_update_ro<<<(NV * 16 + 255) / 256, 256>>>(t16, row_var, adj_var, hvar,
                                                            b_c2v + r * 64, W_ro, b_ro,
                                                            scores, NV);
        }
    }
}

// round 15
// speedup vs baseline: 1.0285x; 1.0285x over previous
#include <cuda_runtime.h>
#include <cuda_fp16.h>
#include <math.h>
#include <string.h>

#define NV 200000
#define NC 100000
#define NE 1200000
#define VFEAT 7
#define CFEAT 5
#define HDIM 64
#define NROUNDS 2
#define SCAN_TILE 2048
#define NBC_ ((NC + SCAN_TILE - 1) / SCAN_TILE)   // 49
#define NBV_ ((NV + SCAN_TILE - 1) / SCAN_TILE)   // 98
#define GPAD 68
#define XPAD 136

typedef unsigned long long ull;

// ---------------- fast helpers ----------------
__device__ __forceinline__ float fast_tanh(float x) {
    float y;
    asm("tanh.approx.f32 %0, %1;" : "=f"(y) : "f"(x));
    return y;
}
__device__ __forceinline__ ull bcast2(float x) {
    ull r;
    unsigned u = __float_as_uint(x);
    asm("mov.b64 %0, {%1, %1};" : "=l"(r) : "r"(u));
    return r;
}
__device__ __forceinline__ void ffma2(ull& d, ull a, ull b) {
    asm("fma.rn.f32x2 %0, %1, %2, %0;" : "+l"(d) : "l"(a), "l"(b));
}
__device__ __forceinline__ float2 unpack2(ull v) {
    float2 f;
    memcpy(&f, &v, 8);
    return f;
}
__device__ __forceinline__ unsigned packh2(float a, float b) {
    __half2 h = __floats2half2_rn(a, b);
    unsigned u;
    memcpy(&u, &h, 4);
    return u;
}
__device__ __forceinline__ float4 cvt_h4(uint2 u) {
    __half2 h0, h1;
    memcpy(&h0, &u.x, 4);
    memcpy(&h1, &u.y, 4);
    float2 a = __half22float2(h0);
    float2 b = __half22float2(h1);
    return make_float4(a.x, a.y, b.x, b.y);
}

// ---------------- device scratch ----------------
__device__ float  g_hvar[NV * HDIM];
__device__ float  g_hcon[NC * HDIM];
__device__ float  g_t[NV * HDIM];       // fp32 agg buffer (con side)
__device__ __half g_t16[NC * HDIM];     // fp16 messages (var side gathers these)
__device__ int   g_deg_var[NV];         // zero-init; self-restoring (fill consumes to 0)
__device__ int   g_deg_con[NC];         // zero-init; self-restoring
__device__ int   g_row_var[NV + 1];
__device__ int   g_row_con[NC + 1];
__device__ int   g_adj_var[NE];
__device__ int   g_adj_con[NE];
__device__ int   g_bsum_var[128];
__device__ int   g_bsum_con[64];

// ---------------- per-side histogram ----------------
__global__ void k_hist1(const int* __restrict__ idx, int* __restrict__ deg) {
    int e = blockIdx.x * blockDim.x + threadIdx.x;
    if (e < NE) atomicAdd(&deg[idx[e]], 1);
}

// ---------------- scan phase A ----------------
__global__ void k_scan_a(const int* __restrict__ deg, int n, int* __restrict__ bsum) {
    __shared__ int ws[8];
    int idx0 = blockIdx.x * SCAN_TILE + threadIdx.x * 8;
    int local = 0;
    #pragma unroll
    for (int i = 0; i < 8; i++) {
        int id = idx0 + i;
        if (id < n) local += deg[id];
    }
    int lane = threadIdx.x & 31, w = threadIdx.x >> 5;
    #pragma unroll
    for (int o = 16; o; o >>= 1) local += __shfl_xor_sync(0xffffffffu, local, o);
    if (lane == 0) ws[w] = local;
    __syncthreads();
    if (threadIdx.x == 0) {
        int s = 0;
        #pragma unroll
        for (int i = 0; i < 8; i++) s += ws[i];
        bsum[blockIdx.x] = s;
    }
}

// ---------------- scan phase B ----------------
__global__ void k_scan_b(int* bsum, int nb) {
    __shared__ int ws[4];
    int tid = threadIdx.x;
    int v = (tid < nb) ? bsum[tid] : 0;
    int lane = tid & 31, w = tid >> 5;
    int inc = v;
    #pragma unroll
    for (int o = 1; o < 32; o <<= 1) {
        int y = __shfl_up_sync(0xffffffffu, inc, o);
        if (lane >= o) inc += y;
    }
    if (lane == 31) ws[w] = inc;
    __syncthreads();
    int add = 0;
    for (int i = 0; i < w; i++) add += ws[i];
    if (tid < nb) bsum[tid] = inc - v + add;
}

// ---------------- scan phase C ----------------
__global__ void k_scan_c(const int* __restrict__ deg, int* __restrict__ row,
                         const int* __restrict__ bsum, int n) {
    __shared__ int wsum[8];
    int idx0 = blockIdx.x * SCAN_TILE + threadIdx.x * 8;
    int pre[8];
    int local = 0;
    #pragma unroll
    for (int i = 0; i < 8; i++) {
        int id = idx0 + i;
        int x = (id < n) ? deg[id] : 0;
        pre[i] = local;
        local += x;
    }
    int lane = threadIdx.x & 31, w = threadIdx.x >> 5;
    int inc = local;
    #pragma unroll
    for (int o = 1; o < 32; o <<= 1) {
        int y = __shfl_up_sync(0xffffffffu, inc, o);
        if (lane >= o) inc += y;
    }
    if (lane == 31) wsum[w] = inc;
    __syncthreads();
    int add = 0;
    for (int i = 0; i < w; i++) add += wsum[i];
    int texcl = bsum[blockIdx.x] + add + (inc - local);
    #pragma unroll
    for (int i = 0; i < 8; i++) {
        int id = idx0 + i;
        if (id < n) row[id] = texcl + pre[i];
    }
    if (blockIdx.x == 0 && threadIdx.x == 0) row[n] = NE;
}

// ---------------- per-side CSR fill (consumes deg via atomicSub -> leaves deg at 0) ----------------
__global__ void k_fill1(const int* __restrict__ key, const int* __restrict__ val,
                        const int* __restrict__ rowp, int* __restrict__ deg,
                        int* __restrict__ adj) {
    int e = blockIdx.x * blockDim.x + threadIdx.x;
    if (e < NE) {
        int k = key[e];
        int p = rowp[k] + (atomicSub(&deg[k], 1) - 1);
        adj[p] = val[e];
    }
}

// ---------------- 8x8-tile 64x64 GEMM core ----------------
__device__ __forceinline__ void gemm64_8x8(
    const float* Wt, const float* Xt, int j0, int n0, ull acc[8][4]) {
    #pragma unroll
    for (int a = 0; a < 8; a++) { acc[a][0] = 0ull; acc[a][1] = 0ull; acc[a][2] = 0ull; acc[a][3] = 0ull; }
    #pragma unroll 8
    for (int k = 0; k < 64; k++) {
        const float* wr = Wt + k * GPAD + j0;
        ulonglong2 wa = *(const ulonglong2*)wr;
        ulonglong2 wb = *(const ulonglong2*)(wr + 4);
        const float* xr = Xt + k * XPAD + n0;
        float4 xa = *(const float4*)xr;
        float4 xb = *(const float4*)(xr + 4);
        float xs[8] = {xa.x, xa.y, xa.z, xa.w, xb.x, xb.y, xb.z, xb.w};
        #pragma unroll
        for (int ni = 0; ni < 8; ni++) {
            ull xp = bcast2(xs[ni]);
            ffma2(acc[ni][0], xp, wa.x);
            ffma2(acc[ni][1], xp, wa.y);
            ffma2(acc[ni][2], xp, wb.x);
            ffma2(acc[ni][3], xp, wb.y);
        }
    }
}

// ---------------- fused encoder ----------------
template <int F>
__global__ __launch_bounds__(128) void k_enc(
    const float* __restrict__ x, const float* __restrict__ W1,
    const float* __restrict__ b1, const float* __restrict__ W2,
    const float* __restrict__ b2, float* __restrict__ out, int n) {
    extern __shared__ float sm[];
    float* W1s = sm;
    float* b1s = sm + 64 * F;
    float* W2t = sm + 64 * F + 64;
    float* Xt  = sm + 64 * F + 64 + 64 * GPAD;
    int tid = threadIdx.x;
    int row0 = blockIdx.x * 128;
    for (int i = tid; i < 64 * F; i += 128) W1s[i] = W1[i];
    if (tid < 64) b1s[tid] = b1[tid];
    #pragma unroll
    for (int i = tid; i < 4096; i += 128) {
        int j = i >> 6, k = i & 63;
        W2t[k * GPAD + j] = W2[i];
    }
    float xf[F];
    {
        int row = row0 + tid;
        if (row < n) {
            #pragma unroll
            for (int f = 0; f < F; f++) xf[f] = x[(size_t)row * F + f];
        } else {
            #pragma unroll
            for (int f = 0; f < F; f++) xf[f] = 0.f;
        }
    }
    __syncthreads();
    {
        int row = row0 + tid;
        if (row < n) {
            #pragma unroll 4
            for (int k = 0; k < 64; k++) {
                float a = b1s[k];
                #pragma unroll
                for (int f = 0; f < F; f++) a += xf[f] * W1s[k * F + f];
                Xt[k * XPAD + tid] = fast_tanh(a);
            }
        } else {
            #pragma unroll 8
            for (int k = 0; k < 64; k++) Xt[k * XPAD + tid] = 0.f;
        }
    }
    __syncthreads();
    const int j0 = (tid & 7) * 8;
    const int n0 = (tid >> 3) * 8;
    ull acc[8][4];
    gemm64_8x8(W2t, Xt, j0, n0, acc);
    float4 ba = *(const float4*)&b2[j0];
    float4 bb = *(const float4*)&b2[j0 + 4];
    #pragma unroll
    for (int ni = 0; ni < 8; ni++) {
        int row = row0 + n0 + ni;
        if (row >= n) break;
        float2 p0 = unpack2(acc[ni][0]), p1 = unpack2(acc[ni][1]);
        float2 p2 = unpack2(acc[ni][2]), p3 = unpack2(acc[ni][3]);
        *(float4*)&out[(size_t)row * 64 + j0]     = make_float4(p0.x + ba.x, p0.y + ba.y, p1.x + ba.z, p1.y + ba.w);
        *(float4*)&out[(size_t)row * 64 + j0 + 4] = make_float4(p2.x + bb.x, p2.y + bb.y, p3.x + bb.z, p3.y + bb.w);
    }
}

// ---------------- fused round GEMM pair (single weight buffer; fp16 msg out) ----------------
__global__ __launch_bounds__(128) void k_gemm_pair(
    const float* __restrict__ agg, const float* __restrict__ W1,
    const float* __restrict__ b1, const int* __restrict__ rowp,
    float* hcon, const float* __restrict__ W2, __half* __restrict__ tout16, int n) {
    extern __shared__ float sm[];
    float* Wt   = sm;                            // 64*GPAD (holds W1, then W2)
    float* Xt   = sm + 64 * GPAD;                // 64*XPAD
    float* degs = sm + 64 * GPAD + 64 * XPAD;    // 128
    int tid = threadIdx.x;
    int row0 = blockIdx.x * 128;
    #pragma unroll
    for (int i = tid; i < 4096; i += 128) {
        int j = i >> 6, k = i & 63;
        Wt[k * GPAD + j] = W1[i];
    }
    {
        int r = tid, row = row0 + r;
        if (row < n) {
            const float4* s4 = (const float4*)(agg + (size_t)row * 64);
            #pragma unroll
            for (int kk = 0; kk < 16; kk++) {
                float4 v = s4[kk];
                Xt[(kk * 4 + 0) * XPAD + r] = v.x;
                Xt[(kk * 4 + 1) * XPAD + r] = v.y;
                Xt[(kk * 4 + 2) * XPAD + r] = v.z;
                Xt[(kk * 4 + 3) * XPAD + r] = v.w;
            }
            degs[r] = (float)(rowp[row + 1] - rowp[row]);
        } else {
            #pragma unroll 8
            for (int k = 0; k < 64; k++) Xt[k * XPAD + r] = 0.f;
            degs[r] = 0.f;
        }
    }
    __syncthreads();
    const int j0 = (tid & 7) * 8;
    const int n0 = (tid >> 3) * 8;
    ull acc[8][4];
    gemm64_8x8(Wt, Xt, j0, n0, acc);
    __syncthreads();   // all Wt/Xt reads of GEMM1 done
    // reload weight buffer with W2 while epilogue runs
    #pragma unroll
    for (int i = tid; i < 4096; i += 128) {
        int j = i >> 6, k = i & 63;
        Wt[k * GPAD + j] = W2[i];
    }
    float4 ba = *(const float4*)&b1[j0];
    float4 bb = *(const float4*)&b1[j0 + 4];
    #pragma unroll
    for (int ni = 0; ni < 8; ni++) {
        int row = row0 + n0 + ni;
        float h[8];
        float2 p0 = unpack2(acc[ni][0]), p1 = unpack2(acc[ni][1]);
        float2 p2 = unpack2(acc[ni][2]), p3 = unpack2(acc[ni][3]);
        h[0] = p0.x; h[1] = p0.y; h[2] = p1.x; h[3] = p1.y;
        h[4] = p2.x; h[5] = p2.y; h[6] = p3.x; h[7] = p3.y;
        if (row < n) {
            float s = degs[n0 + ni];
            float4 r0 = *(const float4*)&hcon[(size_t)row * 64 + j0];
            float4 r1 = *(const float4*)&hcon[(size_t)row * 64 + j0 + 4];
            h[0] = fast_tanh(h[0] + ba.x * s + r0.x);
            h[1] = fast_tanh(h[1] + ba.y * s + r0.y);
            h[2] = fast_tanh(h[2] + ba.z * s + r0.z);
            h[3] = fast_tanh(h[3] + ba.w * s + r0.w);
            h[4] = fast_tanh(h[4] + bb.x * s + r1.x);
            h[5] = fast_tanh(h[5] + bb.y * s + r1.y);
            h[6] = fast_tanh(h[6] + bb.z * s + r1.z);
            h[7] = fast_tanh(h[7] + bb.w * s + r1.w);
            *(float4*)&hcon[(size_t)row * 64 + j0]     = make_float4(h[0], h[1], h[2], h[3]);
            *(float4*)&hcon[(size_t)row * 64 + j0 + 4] = make_float4(h[4], h[5], h[6], h[7]);
        } else {
            #pragma unroll
            for (int jj = 0; jj < 8; jj++) h[jj] = 0.f;
        }
        #pragma unroll
        for (int jj = 0; jj < 8; jj++) Xt[(j0 + jj) * XPAD + n0 + ni] = h[jj];
    }
    __syncthreads();
    gemm64_8x8(Wt, Xt, j0, n0, acc);
    #pragma unroll
    for (int ni = 0; ni < 8; ni++) {
        int row = row0 + n0 + ni;
        if (row >= n) break;
        float2 p0 = unpack2(acc[ni][0]), p1 = unpack2(acc[ni][1]);
        float2 p2 = unpack2(acc[ni][2]), p3 = unpack2(acc[ni][3]);
        uint4 v;
        v.x = packh2(p0.x, p0.y);
        v.y = packh2(p1.x, p1.y);
        v.z = packh2(p2.x, p2.y);
        v.w = packh2(p3.x, p3.y);
        *(uint4*)&tout16[(size_t)row * 64 + j0] = v;
    }
}

// ---------------- half-warp-per-row gather core (fp32 src) ----------------
__device__ __forceinline__ float4 gather_row_hw(
    const float* __restrict__ src, const int* __restrict__ adj,
    int b, int e, int fl) {
    float4 a0 = make_float4(0.f, 0.f, 0.f, 0.f);
    float4 a1 = a0, a2 = a0, a3 = a0;
    int i = b;
    for (; i + 4 <= e; i += 4) {
        int v0 = adj[i], v1 = adj[i + 1], v2 = adj[i + 2], v3 = adj[i + 3];
        float4 x0 = *(const float4*)&src[(size_t)v0 * 64 + fl * 4];
        float4 x1 = *(const float4*)&src[(size_t)v1 * 64 + fl * 4];
        float4 x2 = *(const float4*)&src[(size_t)v2 * 64 + fl * 4];
        float4 x3 = *(const float4*)&src[(size_t)v3 * 64 + fl * 4];
        a0.x += x0.x; a0.y += x0.y; a0.z += x0.z; a0.w += x0.w;
        a1.x += x1.x; a1.y += x1.y; a1.z += x1.z; a1.w += x1.w;
        a2.x += x2.x; a2.y += x2.y; a2.z += x2.z; a2.w += x2.w;
        a3.x += x3.x; a3.y += x3.y; a3.z += x3.z; a3.w += x3.w;
    }
    for (; i < e; i++) {
        int v = adj[i];
        float4 x = *(const float4*)&src[(size_t)v * 64 + fl * 4];
        a0.x += x.x; a0.y += x.y; a0.z += x.z; a0.w += x.w;
    }
    a0.x = (a0.x + a1.x) + (a2.x + a3.x);
    a0.y = (a0.y + a1.y) + (a2.y + a3.y);
    a0.z = (a0.z + a1.z) + (a2.z + a3.z);
    a0.w = (a0.w + a1.w) + (a2.w + a3.w);
    return a0;
}

// ---------------- half-warp-per-row gather core (fp16 src, fp32 accum) ----------------
__device__ __forceinline__ float4 gather_row_hw_h(
    const __half* __restrict__ src, const int* __restrict__ adj,
    int b, int e, int fl) {
    float4 a0 = make_float4(0.f, 0.f, 0.f, 0.f);
    float4 a1 = a0, a2 = a0, a3 = a0;
    int i = b;
    for (; i + 4 <= e; i += 4) {
        int v0 = adj[i], v1 = adj[i + 1], v2 = adj[i + 2], v3 = adj[i + 3];
        uint2 u0 = *(const uint2*)&src[(size_t)v0 * 64 + fl * 4];
        uint2 u1 = *(const uint2*)&src[(size_t)v1 * 64 + fl * 4];
        uint2 u2 = *(const uint2*)&src[(size_t)v2 * 64 + fl * 4];
        uint2 u3 = *(const uint2*)&src[(size_t)v3 * 64 + fl * 4];
        float4 x0 = cvt_h4(u0), x1 = cvt_h4(u1), x2 = cvt_h4(u2), x3 = cvt_h4(u3);
        a0.x += x0.x; a0.y += x0.y; a0.z += x0.z; a0.w += x0.w;
        a1.x += x1.x; a1.y += x1.y; a1.z += x1.z; a1.w += x1.w;
        a2.x += x2.x; a2.y += x2.y; a2.z += x2.z; a2.w += x2.w;
        a3.x += x3.x; a3.y += x3.y; a3.z += x3.z; a3.w += x3.w;
    }
    for (; i < e; i++) {
        int v = adj[i];
        uint2 u = *(const uint2*)&src[(size_t)v * 64 + fl * 4];
        float4 x = cvt_h4(u);
        a0.x += x.x; a0.y += x.y; a0.z += x.z; a0.w += x.w;
    }
    a0.x = (a0.x + a1.x) + (a2.x + a3.x);
    a0.y = (a0.y + a1.y) + (a2.y + a3.y);
    a0.z = (a0.z + a1.z) + (a2.z + a3.z);
    a0.w = (a0.w + a1.w) + (a2.w + a3.w);
    return a0;
}

// ---------------- gather aggregation (2 rows per warp, fp32 src) ----------------
__global__ __launch_bounds__(256) void k_agg(
    const float* __restrict__ src, const int* __restrict__ rowp,
    const int* __restrict__ adj, float* __restrict__ out, int n) {
    int gw = (blockIdx.x * 256 + threadIdx.x) >> 5;
    int lane = threadIdx.x & 31;
    int half = lane >> 4, fl = lane & 15;
    int row = gw * 2 + half;
    if (gw * 2 >= n) return;
    int b = rowp[row], e = rowp[row + 1];
    float4 a = gather_row_hw(src, adj, b, e, fl);
    *(float4*)&out[(size_t)row * 64 + fl * 4] = a;
}

// ---------------- gather + update (2 rows per warp, fp16 src) ----------------
__global__ __launch_bounds__(256) void k_agg_update(
    const __half* __restrict__ src16, const int* __restrict__ rowp,
    const int* __restrict__ adj, float* h, const float* __restrict__ bias, int n) {
    int gw = (blockIdx.x * 256 + threadIdx.x) >> 5;
    int lane = threadIdx.x & 31;
    int half = lane >> 4, fl = lane & 15;
    int row = gw * 2 + half;
    if (gw * 2 >= n) return;
    int b = rowp[row], e = rowp[row + 1];
    float4 a = gather_row_hw_h(src16, adj, b, e, fl);
    float d = (float)(e - b);
    float4 bb = *(const float4*)&bias[fl * 4];
    float4 hv = *(const float4*)&h[(size_t)row * 64 + fl * 4];
    hv.x = fast_tanh(hv.x + a.x + d * bb.x);
    hv.y = fast_tanh(hv.y + a.y + d * bb.y);
    hv.z = fast_tanh(hv.z + a.z + d * bb.z);
    hv.w = fast_tanh(hv.w + a.w + d * bb.w);
    *(float4*)&h[(size_t)row * 64 + fl * 4] = hv;
}

// ---------------- final: gather + update + readout (2 rows per warp, fp16 src) ----------------
__global__ __launch_bounds__(256) void k_agg_update_ro(
    const __half* __restrict__ src16, const int* __restrict__ rowp,
    const int* __restrict__ adj, const float* __restrict__ h,
    const float* __restrict__ bias, const float* __restrict__ Wro,
    const float* __restrict__ bro, float* __restrict__ scores, int n) {
    int gw = (blockIdx.x * 256 + threadIdx.x) >> 5;
    int lane = threadIdx.x & 31;
    int half = lane >> 4, fl = lane & 15;
    int row = gw * 2 + half;
    if (gw * 2 >= n) return;
    int b = rowp[row], e = rowp[row + 1];
    float4 a = gather_row_hw_h(src16, adj, b, e, fl);
    float d = (float)(e - b);
    float4 bb = *(const float4*)&bias[fl * 4];
    float4 hv = *(const float4*)&h[(size_t)row * 64 + fl * 4];
    float4 ww = *(const float4*)&Wro[fl * 4];
    float hx = fast_tanh(hv.x + a.x + d * bb.x);
    float hy = fast_tanh(hv.y + a.y + d * bb.y);
    float hz = fast_tanh(hv.z + a.z + d * bb.z);
    float hw = fast_tanh(hv.w + a.w + d * bb.w);
    float s = hx * ww.x + hy * ww.y + hz * ww.z + hw * ww.w;
    #pragma unroll
    for (int o = 8; o; o >>= 1) s += __shfl_xor_sync(0xffffffffu, s, o);
    if (fl == 0) scores[row] = s + bro[0];
}

// ---------------- launch ----------------
extern "C" void kernel_launch(void* const* d_in, const int* in_sizes, int n_in,
                              void* d_out, int out_size) {
    const float* var_features = (const float*)d_in[0];
    const float* con_features = (const float*)d_in[1];
    const int*   edge_var     = (const int*)d_in[2];
    const int*   edge_con     = (const int*)d_in[3];
    const float* W_ve1 = (const float*)d_in[4];
    const float* b_ve1 = (const float*)d_in[5];
    const float* W_ve2 = (const float*)d_in[6];
    const float* b_ve2 = (const float*)d_in[7];
    const float* W_ce1 = (const float*)d_in[8];
    const float* b_ce1 = (const float*)d_in[9];
    const float* W_ce2 = (const float*)d_in[10];
    const float* b_ce2 = (const float*)d_in[11];
    const float* W_v2c = (const float*)d_in[12];
    const float* b_v2c = (const float*)d_in[13];
    const float* W_c2v = (const float*)d_in[14];
    const float* b_c2v = (const float*)d_in[15];
    const float* W_ro  = (const float*)d_in[16];
    const float* b_ro  = (const float*)d_in[17];
    float* scores = (float*)d_out;

    float *hvar, *hcon, *tbuf;
    __half* t16;
    int *row_var, *row_con, *adj_var, *adj_con, *deg_var, *deg_con, *bsv, *bsc;
    cudaGetSymbolAddress((void**)&hvar, g_hvar);
    cudaGetSymbolAddress((void**)&hcon, g_hcon);
    cudaGetSymbolAddress((void**)&tbuf, g_t);
    cudaGetSymbolAddress((void**)&t16, g_t16);
    cudaGetSymbolAddress((void**)&row_var, g_row_var);
    cudaGetSymbolAddress((void**)&row_con, g_row_con);
    cudaGetSymbolAddress((void**)&adj_var, g_adj_var);
    cudaGetSymbolAddress((void**)&adj_con, g_adj_con);
    cudaGetSymbolAddress((void**)&deg_var, g_deg_var);
    cudaGetSymbolAddress((void**)&deg_con, g_deg_con);
    cudaGetSymbolAddress((void**)&bsv, g_bsum_var);
    cudaGetSymbolAddress((void**)&bsc, g_bsum_con);

    const int GEMM_SMEM = (64 * GPAD + 64 * XPAD + 128) * sizeof(float);   // 52736
    const int ENCV_SMEM = (64 * VFEAT + 64 + 64 * GPAD + 64 * XPAD) * sizeof(float);
    const int ENCC_SMEM = (64 * CFEAT + 64 + 64 * GPAD + 64 * XPAD) * sizeof(float);
    cudaFuncSetAttribute((const void*)k_gemm_pair, cudaFuncAttributeMaxDynamicSharedMemorySize, GEMM_SMEM);
    cudaFuncSetAttribute((const void*)k_enc<VFEAT>, cudaFuncAttributeMaxDynamicSharedMemorySize, ENCV_SMEM);
    cudaFuncSetAttribute((const void*)k_enc<CFEAT>, cudaFuncAttributeMaxDynamicSharedMemorySize, ENCC_SMEM);

    // ---- single side stream ----
    cudaStream_t s2;
    cudaStreamCreateWithFlags(&s2, cudaStreamNonBlocking);
    cudaEvent_t evFork, evEnc, evVar;
    cudaEventCreateWithFlags(&evFork, cudaEventDisableTiming);
    cudaEventCreateWithFlags(&evEnc, cudaEventDisableTiming);
    cudaEventCreateWithFlags(&evVar, cudaEventDisableTiming);
    cudaEventRecord(evFork, 0);
    cudaStreamWaitEvent(s2, evFork, 0);

    // s2: encoders, then var-side CSR chain (deg_var is self-restoring; no zeroing)
    k_enc<VFEAT><<<(NV + 127) / 128, 128, ENCV_SMEM, s2>>>(var_features, W_ve1, b_ve1, W_ve2, b_ve2, hvar, NV);
    k_enc<CFEAT><<<(NC + 127) / 128, 128, ENCC_SMEM, s2>>>(con_features, W_ce1, b_ce1, W_ce2, b_ce2, hcon, NC);
    cudaEventRecord(evEnc, s2);
    k_hist1<<<(NE + 255) / 256, 256, 0, s2>>>(edge_var, deg_var);
    k_scan_a<<<NBV_, 256, 0, s2>>>(deg_var, NV, bsv);
    k_scan_b<<<1, 128, 0, s2>>>(bsv, NBV_);
    k_scan_c<<<NBV_, 256, 0, s2>>>(deg_var, row_var, bsv, NV);
    k_fill1<<<(NE + 255) / 256, 256, 0, s2>>>(edge_var, edge_con, row_var, deg_var, adj_var);
    cudaEventRecord(evVar, s2);

    // main: con-side CSR chain (deg_con self-restoring)
    k_hist1<<<(NE + 255) / 256, 256>>>(edge_con, deg_con);
    k_scan_a<<<NBC_, 256>>>(deg_con, NC, bsc);
    k_scan_b<<<1, 128>>>(bsc, NBC_);
    k_scan_c<<<NBC_, 256>>>(deg_con, row_con, bsc, NC);
    k_fill1<<<(NE + 255) / 256, 256>>>(edge_con, edge_var, row_con, deg_con, adj_con);

    // join encoders before round loop
    cudaStreamWaitEvent(0, evEnc, 0);

    // ---- message passing rounds ----
    for (int r = 0; r < NROUNDS; r++) {
        k_agg<<<(NC * 16 + 255) / 256, 256>>>(hvar, row_con, adj_con, tbuf, NC);
        k_gemm_pair<<<(NC + 127) / 128, 128, GEMM_SMEM>>>(tbuf, W_v2c + r * 4096, b_v2c + r * 64,
                                                          row_con, hcon, W_c2v + r * 4096, t16, NC);
        if (r == 0) cudaStreamWaitEvent(0, evVar, 0);   // late join of var CSR chain
        if (r < NROUNDS - 1) {
            k_agg_update<<<(NV * 16 + 255) / 256, 256>>>(t16, row_var, adj_var, hvar,
                                                         b_c2v + r * 64, NV);
        } else {
            k_agg_update_ro<<<(NV * 16 + 255) / 256, 256>>>(t16, row_var, adj_var, hvar,
                                                            b_c2v + r * 64, W_ro, b_ro,
                                                            scores, NV);
        }
    }
}

// round 16
// speedup vs baseline: 1.0453x; 1.0164x over previous
#include <cuda_runtime.h>
#include <cuda_fp16.h>
#include <math.h>
#include <string.h>

#define NV 200000
#define NC 100000
#define NE 1200000
#define VFEAT 7
#define CFEAT 5
#define HDIM 64
#define NROUNDS 2
#define SCAN_TILE 2048
#define NBC_ ((NC + SCAN_TILE - 1) / SCAN_TILE)   // 49
#define NBV_ ((NV + SCAN_TILE - 1) / SCAN_TILE)   // 98
#define GPAD 68
#define XPAD 136

typedef unsigned long long ull;

// ---------------- fast helpers ----------------
__device__ __forceinline__ float fast_tanh(float x) {
    float y;
    asm("tanh.approx.f32 %0, %1;" : "=f"(y) : "f"(x));
    return y;
}
__device__ __forceinline__ ull bcast2(float x) {
    ull r;
    unsigned u = __float_as_uint(x);
    asm("mov.b64 %0, {%1, %1};" : "=l"(r) : "r"(u));
    return r;
}
__device__ __forceinline__ void ffma2(ull& d, ull a, ull b) {
    asm("fma.rn.f32x2 %0, %1, %2, %0;" : "+l"(d) : "l"(a), "l"(b));
}
__device__ __forceinline__ float2 unpack2(ull v) {
    float2 f;
    memcpy(&f, &v, 8);
    return f;
}
__device__ __forceinline__ unsigned packh2(float a, float b) {
    __half2 h = __floats2half2_rn(a, b);
    unsigned u;
    memcpy(&u, &h, 4);
    return u;
}
__device__ __forceinline__ float4 cvt_h4(uint2 u) {
    __half2 h0, h1;
    memcpy(&h0, &u.x, 4);
    memcpy(&h1, &u.y, 4);
    float2 a = __half22float2(h0);
    float2 b = __half22float2(h1);
    return make_float4(a.x, a.y, b.x, b.y);
}

// ---------------- device scratch ----------------
__device__ float  g_hvar[NV * HDIM];
__device__ float  g_hcon[NC * HDIM];
__device__ float  g_t[NV * HDIM];       // fp32 agg buffer (con side)
__device__ __half g_t16[NC * HDIM];     // fp16 messages (var side gathers these)
__device__ int   g_deg_var[NV];         // zero-init; self-restoring (fill consumes to 0)
__device__ int   g_deg_con[NC];         // zero-init; self-restoring
__device__ int   g_row_var[NV + 1];
__device__ int   g_row_con[NC + 1];
__device__ int   g_adj_var[NE];
__device__ int   g_adj_con[NE];
__device__ int   g_bsum_var[128];
__device__ int   g_bsum_con[64];

// ---------------- per-side histogram ----------------
__global__ void k_hist1(const int* __restrict__ idx, int* __restrict__ deg) {
    int e = blockIdx.x * blockDim.x + threadIdx.x;
    if (e < NE) atomicAdd(&deg[idx[e]], 1);
}

// ---------------- scan phase A ----------------
__global__ void k_scan_a(const int* __restrict__ deg, int n, int* __restrict__ bsum) {
    __shared__ int ws[8];
    int idx0 = blockIdx.x * SCAN_TILE + threadIdx.x * 8;
    int local = 0;
    #pragma unroll
    for (int i = 0; i < 8; i++) {
        int id = idx0 + i;
        if (id < n) local += deg[id];
    }
    int lane = threadIdx.x & 31, w = threadIdx.x >> 5;
    #pragma unroll
    for (int o = 16; o; o >>= 1) local += __shfl_xor_sync(0xffffffffu, local, o);
    if (lane == 0) ws[w] = local;
    __syncthreads();
    if (threadIdx.x == 0) {
        int s = 0;
        #pragma unroll
        for (int i = 0; i < 8; i++) s += ws[i];
        bsum[blockIdx.x] = s;
    }
}

// ---------------- scan phase B ----------------
__global__ void k_scan_b(int* bsum, int nb) {
    __shared__ int ws[4];
    int tid = threadIdx.x;
    int v = (tid < nb) ? bsum[tid] : 0;
    int lane = tid & 31, w = tid >> 5;
    int inc = v;
    #pragma unroll
    for (int o = 1; o < 32; o <<= 1) {
        int y = __shfl_up_sync(0xffffffffu, inc, o);
        if (lane >= o) inc += y;
    }
    if (lane == 31) ws[w] = inc;
    __syncthreads();
    int add = 0;
    for (int i = 0; i < w; i++) add += ws[i];
    if (tid < nb) bsum[tid] = inc - v + add;
}

// ---------------- scan phase C ----------------
__global__ void k_scan_c(const int* __restrict__ deg, int* __restrict__ row,
                         const int* __restrict__ bsum, int n) {
    __shared__ int wsum[8];
    int idx0 = blockIdx.x * SCAN_TILE + threadIdx.x * 8;
    int pre[8];
    int local = 0;
    #pragma unroll
    for (int i = 0; i < 8; i++) {
        int id = idx0 + i;
        int x = (id < n) ? deg[id] : 0;
        pre[i] = local;
        local += x;
    }
    int lane = threadIdx.x & 31, w = threadIdx.x >> 5;
    int inc = local;
    #pragma unroll
    for (int o = 1; o < 32; o <<= 1) {
        int y = __shfl_up_sync(0xffffffffu, inc, o);
        if (lane >= o) inc += y;
    }
    if (lane == 31) wsum[w] = inc;
    __syncthreads();
    int add = 0;
    for (int i = 0; i < w; i++) add += wsum[i];
    int texcl = bsum[blockIdx.x] + add + (inc - local);
    #pragma unroll
    for (int i = 0; i < 8; i++) {
        int id = idx0 + i;
        if (id < n) row[id] = texcl + pre[i];
    }
    if (blockIdx.x == 0 && threadIdx.x == 0) row[n] = NE;
}

// ---------------- per-side CSR fill (consumes deg via atomicSub -> leaves deg at 0) ----------------
__global__ void k_fill1(const int* __restrict__ key, const int* __restrict__ val,
                        const int* __restrict__ rowp, int* __restrict__ deg,
                        int* __restrict__ adj) {
    int e = blockIdx.x * blockDim.x + threadIdx.x;
    if (e < NE) {
        int k = key[e];
        int p = rowp[k] + (atomicSub(&deg[k], 1) - 1);
        adj[p] = val[e];
    }
}

// ---------------- 8x8-tile 64x64 GEMM core ----------------
__device__ __forceinline__ void gemm64_8x8(
    const float* Wt, const float* Xt, int j0, int n0, ull acc[8][4]) {
    #pragma unroll
    for (int a = 0; a < 8; a++) { acc[a][0] = 0ull; acc[a][1] = 0ull; acc[a][2] = 0ull; acc[a][3] = 0ull; }
    #pragma unroll 8
    for (int k = 0; k < 64; k++) {
        const float* wr = Wt + k * GPAD + j0;
        ulonglong2 wa = *(const ulonglong2*)wr;
        ulonglong2 wb = *(const ulonglong2*)(wr + 4);
        const float* xr = Xt + k * XPAD + n0;
        float4 xa = *(const float4*)xr;
        float4 xb = *(const float4*)(xr + 4);
        float xs[8] = {xa.x, xa.y, xa.z, xa.w, xb.x, xb.y, xb.z, xb.w};
        #pragma unroll
        for (int ni = 0; ni < 8; ni++) {
            ull xp = bcast2(xs[ni]);
            ffma2(acc[ni][0], xp, wa.x);
            ffma2(acc[ni][1], xp, wa.y);
            ffma2(acc[ni][2], xp, wb.x);
            ffma2(acc[ni][3], xp, wb.y);
        }
    }
}

// ---------------- fused encoder ----------------
template <int F>
__global__ __launch_bounds__(128) void k_enc(
    const float* __restrict__ x, const float* __restrict__ W1,
    const float* __restrict__ b1, const float* __restrict__ W2,
    const float* __restrict__ b2, float* __restrict__ out, int n) {
    extern __shared__ float sm[];
    float* W1s = sm;
    float* b1s = sm + 64 * F;
    float* W2t = sm + 64 * F + 64;
    float* Xt  = sm + 64 * F + 64 + 64 * GPAD;
    int tid = threadIdx.x;
    int row0 = blockIdx.x * 128;
    for (int i = tid; i < 64 * F; i += 128) W1s[i] = W1[i];
    if (tid < 64) b1s[tid] = b1[tid];
    #pragma unroll
    for (int i = tid; i < 4096; i += 128) {
        int j = i >> 6, k = i & 63;
        W2t[k * GPAD + j] = W2[i];
    }
    float xf[F];
    {
        int row = row0 + tid;
        if (row < n) {
            #pragma unroll
            for (int f = 0; f < F; f++) xf[f] = x[(size_t)row * F + f];
        } else {
            #pragma unroll
            for (int f = 0; f < F; f++) xf[f] = 0.f;
        }
    }
    __syncthreads();
    {
        int row = row0 + tid;
        if (row < n) {
            #pragma unroll 4
            for (int k = 0; k < 64; k++) {
                float a = b1s[k];
                #pragma unroll
                for (int f = 0; f < F; f++) a += xf[f] * W1s[k * F + f];
                Xt[k * XPAD + tid] = fast_tanh(a);
            }
        } else {
            #pragma unroll 8
            for (int k = 0; k < 64; k++) Xt[k * XPAD + tid] = 0.f;
        }
    }
    __syncthreads();
    const int j0 = (tid & 7) * 8;
    const int n0 = (tid >> 3) * 8;
    ull acc[8][4];
    gemm64_8x8(W2t, Xt, j0, n0, acc);
    float4 ba = *(const float4*)&b2[j0];
    float4 bb = *(const float4*)&b2[j0 + 4];
    #pragma unroll
    for (int ni = 0; ni < 8; ni++) {
        int row = row0 + n0 + ni;
        if (row >= n) break;
        float2 p0 = unpack2(acc[ni][0]), p1 = unpack2(acc[ni][1]);
        float2 p2 = unpack2(acc[ni][2]), p3 = unpack2(acc[ni][3]);
        *(float4*)&out[(size_t)row * 64 + j0]     = make_float4(p0.x + ba.x, p0.y + ba.y, p1.x + ba.z, p1.y + ba.w);
        *(float4*)&out[(size_t)row * 64 + j0 + 4] = make_float4(p2.x + bb.x, p2.y + bb.y, p3.x + bb.z, p3.y + bb.w);
    }
}

// ---------------- fused round GEMM pair (dual weight buffers; fp16 msg out) ----------------
__global__ __launch_bounds__(128) void k_gemm_pair(
    const float* __restrict__ agg, const float* __restrict__ W1,
    const float* __restrict__ b1, const int* __restrict__ rowp,
    float* hcon, const float* __restrict__ W2, __half* __restrict__ tout16, int n) {
    extern __shared__ float sm[];
    float* W1t  = sm;
    float* W2t  = sm + 64 * GPAD;
    float* Xt   = sm + 2 * 64 * GPAD;
    float* degs = sm + 2 * 64 * GPAD + 64 * XPAD;
    int tid = threadIdx.x;
    int row0 = blockIdx.x * 128;
    #pragma unroll
    for (int i = tid; i < 4096; i += 128) {
        int j = i >> 6, k = i & 63;
        W1t[k * GPAD + j] = W1[i];
        W2t[k * GPAD + j] = W2[i];
    }
    {
        int r = tid, row = row0 + r;
        if (row < n) {
            const float4* s4 = (const float4*)(agg + (size_t)row * 64);
            #pragma unroll
            for (int kk = 0; kk < 16; kk++) {
                float4 v = s4[kk];
                Xt[(kk * 4 + 0) * XPAD + r] = v.x;
                Xt[(kk * 4 + 1) * XPAD + r] = v.y;
                Xt[(kk * 4 + 2) * XPAD + r] = v.z;
                Xt[(kk * 4 + 3) * XPAD + r] = v.w;
            }
            degs[r] = (float)(rowp[row + 1] - rowp[row]);
        } else {
            #pragma unroll 8
            for (int k = 0; k < 64; k++) Xt[k * XPAD + r] = 0.f;
            degs[r] = 0.f;
        }
    }
    __syncthreads();
    const int j0 = (tid & 7) * 8;
    const int n0 = (tid >> 3) * 8;
    ull acc[8][4];
    gemm64_8x8(W1t, Xt, j0, n0, acc);
    __syncthreads();
    float4 ba = *(const float4*)&b1[j0];
    float4 bb = *(const float4*)&b1[j0 + 4];
    #pragma unroll
    for (int ni = 0; ni < 8; ni++) {
        int row = row0 + n0 + ni;
        float h[8];
        float2 p0 = unpack2(acc[ni][0]), p1 = unpack2(acc[ni][1]);
        float2 p2 = unpack2(acc[ni][2]), p3 = unpack2(acc[ni][3]);
        h[0] = p0.x; h[1] = p0.y; h[2] = p1.x; h[3] = p1.y;
        h[4] = p2.x; h[5] = p2.y; h[6] = p3.x; h[7] = p3.y;
        if (row < n) {
            float s = degs[n0 + ni];
            float4 r0 = *(const float4*)&hcon[(size_t)row * 64 + j0];
            float4 r1 = *(const float4*)&hcon[(size_t)row * 64 + j0 + 4];
            h[0] = fast_tanh(h[0] + ba.x * s + r0.x);
            h[1] = fast_tanh(h[1] + ba.y * s + r0.y);
            h[2] = fast_tanh(h[2] + ba.z * s + r0.z);
            h[3] = fast_tanh(h[3] + ba.w * s + r0.w);
            h[4] = fast_tanh(h[4] + bb.x * s + r1.x);
            h[5] = fast_tanh(h[5] + bb.y * s + r1.y);
            h[6] = fast_tanh(h[6] + bb.z * s + r1.z);
            h[7] = fast_tanh(h[7] + bb.w * s + r1.w);
            *(float4*)&hcon[(size_t)row * 64 + j0]     = make_float4(h[0], h[1], h[2], h[3]);
            *(float4*)&hcon[(size_t)row * 64 + j0 + 4] = make_float4(h[4], h[5], h[6], h[7]);
        } else {
            #pragma unroll
            for (int jj = 0; jj < 8; jj++) h[jj] = 0.f;
        }
        #pragma unroll
        for (int jj = 0; jj < 8; jj++) Xt[(j0 + jj) * XPAD + n0 + ni] = h[jj];
    }
    __syncthreads();
    gemm64_8x8(W2t, Xt, j0, n0, acc);
    #pragma unroll
    for (int ni = 0; ni < 8; ni++) {
        int row = row0 + n0 + ni;
        if (row >= n) break;
        float2 p0 = unpack2(acc[ni][0]), p1 = unpack2(acc[ni][1]);
        float2 p2 = unpack2(acc[ni][2]), p3 = unpack2(acc[ni][3]);
        uint4 v;
        v.x = packh2(p0.x, p0.y);
        v.y = packh2(p1.x, p1.y);
        v.z = packh2(p2.x, p2.y);
        v.w = packh2(p3.x, p3.y);
        *(uint4*)&tout16[(size_t)row * 64 + j0] = v;
    }
}

// ---------------- half-warp-per-row gather core (fp32 src) ----------------
__device__ __forceinline__ float4 gather_row_hw(
    const float* __restrict__ src, const int* __restrict__ adj,
    int b, int e, int fl) {
    float4 a0 = make_float4(0.f, 0.f, 0.f, 0.f);
    float4 a1 = a0, a2 = a0, a3 = a0;
    int i = b;
    for (; i + 4 <= e; i += 4) {
        int v0 = adj[i], v1 = adj[i + 1], v2 = adj[i + 2], v3 = adj[i + 3];
        float4 x0 = *(const float4*)&src[(size_t)v0 * 64 + fl * 4];
        float4 x1 = *(const float4*)&src[(size_t)v1 * 64 + fl * 4];
        float4 x2 = *(const float4*)&src[(size_t)v2 * 64 + fl * 4];
        float4 x3 = *(const float4*)&src[(size_t)v3 * 64 + fl * 4];
        a0.x += x0.x; a0.y += x0.y; a0.z += x0.z; a0.w += x0.w;
        a1.x += x1.x; a1.y += x1.y; a1.z += x1.z; a1.w += x1.w;
        a2.x += x2.x; a2.y += x2.y; a2.z += x2.z; a2.w += x2.w;
        a3.x += x3.x; a3.y += x3.y; a3.z += x3.z; a3.w += x3.w;
    }
    for (; i < e; i++) {
        int v = adj[i];
        float4 x = *(const float4*)&src[(size_t)v * 64 + fl * 4];
        a0.x += x.x; a0.y += x.y; a0.z += x.z; a0.w += x.w;
    }
    a0.x = (a0.x + a1.x) + (a2.x + a3.x);
    a0.y = (a0.y + a1.y) + (a2.y + a3.y);
    a0.z = (a0.z + a1.z) + (a2.z + a3.z);
    a0.w = (a0.w + a1.w) + (a2.w + a3.w);
    return a0;
}

// ---------------- half-warp-per-row gather core (fp16 src, fp32 accum) ----------------
__device__ __forceinline__ float4 gather_row_hw_h(
    const __half* __restrict__ src, const int* __restrict__ adj,
    int b, int e, int fl) {
    float4 a0 = make_float4(0.f, 0.f, 0.f, 0.f);
    float4 a1 = a0, a2 = a0, a3 = a0;
    int i = b;
    for (; i + 4 <= e; i += 4) {
        int v0 = adj[i], v1 = adj[i + 1], v2 = adj[i + 2], v3 = adj[i + 3];
        uint2 u0 = *(const uint2*)&src[(size_t)v0 * 64 + fl * 4];
        uint2 u1 = *(const uint2*)&src[(size_t)v1 * 64 + fl * 4];
        uint2 u2 = *(const uint2*)&src[(size_t)v2 * 64 + fl * 4];
        uint2 u3 = *(const uint2*)&src[(size_t)v3 * 64 + fl * 4];
        float4 x0 = cvt_h4(u0), x1 = cvt_h4(u1), x2 = cvt_h4(u2), x3 = cvt_h4(u3);
        a0.x += x0.x; a0.y += x0.y; a0.z += x0.z; a0.w += x0.w;
        a1.x += x1.x; a1.y += x1.y; a1.z += x1.z; a1.w += x1.w;
        a2.x += x2.x; a2.y += x2.y; a2.z += x2.z; a2.w += x2.w;
        a3.x += x3.x; a3.y += x3.y; a3.z += x3.z; a3.w += x3.w;
    }
    for (; i < e; i++) {
        int v = adj[i];
        uint2 u = *(const uint2*)&src[(size_t)v * 64 + fl * 4];
        float4 x = cvt_h4(u);
        a0.x += x.x; a0.y += x.y; a0.z += x.z; a0.w += x.w;
    }
    a0.x = (a0.x + a1.x) + (a2.x + a3.x);
    a0.y = (a0.y + a1.y) + (a2.y + a3.y);
    a0.z = (a0.z + a1.z) + (a2.z + a3.z);
    a0.w = (a0.w + a1.w) + (a2.w + a3.w);
    return a0;
}

// ---------------- gather aggregation (2 rows per warp, fp32 src) ----------------
__global__ __launch_bounds__(256) void k_agg(
    const float* __restrict__ src, const int* __restrict__ rowp,
    const int* __restrict__ adj, float* __restrict__ out, int n) {
    int gw = (blockIdx.x * 256 + threadIdx.x) >> 5;
    int lane = threadIdx.x & 31;
    int half = lane >> 4, fl = lane & 15;
    int row = gw * 2 + half;
    if (gw * 2 >= n) return;
    int b = rowp[row], e = rowp[row + 1];
    float4 a = gather_row_hw(src, adj, b, e, fl);
    *(float4*)&out[(size_t)row * 64 + fl * 4] = a;
}

// ---------------- gather + update (2 rows per warp, fp16 src) ----------------
__global__ __launch_bounds__(256) void k_agg_update(
    const __half* __restrict__ src16, const int* __restrict__ rowp,
    const int* __restrict__ adj, float* h, const float* __restrict__ bias, int n) {
    int gw = (blockIdx.x * 256 + threadIdx.x) >> 5;
    int lane = threadIdx.x & 31;
    int half = lane >> 4, fl = lane & 15;
    int row = gw * 2 + half;
    if (gw * 2 >= n) return;
    int b = rowp[row], e = rowp[row + 1];
    float4 a = gather_row_hw_h(src16, adj, b, e, fl);
    float d = (float)(e - b);
    float4 bb = *(const float4*)&bias[fl * 4];
    float4 hv = *(const float4*)&h[(size_t)row * 64 + fl * 4];
    hv.x = fast_tanh(hv.x + a.x + d * bb.x);
    hv.y = fast_tanh(hv.y + a.y + d * bb.y);
    hv.z = fast_tanh(hv.z + a.z + d * bb.z);
    hv.w = fast_tanh(hv.w + a.w + d * bb.w);
    *(float4*)&h[(size_t)row * 64 + fl * 4] = hv;
}

// ---------------- final: gather + update + readout (2 rows per warp, fp16 src) ----------------
__global__ __launch_bounds__(256) void k_agg_update_ro(
    const __half* __restrict__ src16, const int* __restrict__ rowp,
    const int* __restrict__ adj, const float* __restrict__ h,
    const float* __restrict__ bias, const float* __restrict__ Wro,
    const float* __restrict__ bro, float* __restrict__ scores, int n) {
    int gw = (blockIdx.x * 256 + threadIdx.x) >> 5;
    int lane = threadIdx.x & 31;
    int half = lane >> 4, fl = lane & 15;
    int row = gw * 2 + half;
    if (gw * 2 >= n) return;
    int b = rowp[row], e = rowp[row + 1];
    float4 a = gather_row_hw_h(src16, adj, b, e, fl);
    float d = (float)(e - b);
    float4 bb = *(const float4*)&bias[fl * 4];
    float4 hv = *(const float4*)&h[(size_t)row * 64 + fl * 4];
    float4 ww = *(const float4*)&Wro[fl * 4];
    float hx = fast_tanh(hv.x + a.x + d * bb.x);
    float hy = fast_tanh(hv.y + a.y + d * bb.y);
    float hz = fast_tanh(hv.z + a.z + d * bb.z);
    float hw = fast_tanh(hv.w + a.w + d * bb.w);
    float s = hx * ww.x + hy * ww.y + hz * ww.z + hw * ww.w;
    #pragma unroll
    for (int o = 8; o; o >>= 1) s += __shfl_xor_sync(0xffffffffu, s, o);
    if (fl == 0) scores[row] = s + bro[0];
}

// ---------------- launch ----------------
extern "C" void kernel_launch(void* const* d_in, const int* in_sizes, int n_in,
                              void* d_out, int out_size) {
    const float* var_features = (const float*)d_in[0];
    const float* con_features = (const float*)d_in[1];
    const int*   edge_var     = (const int*)d_in[2];
    const int*   edge_con     = (const int*)d_in[3];
    const float* W_ve1 = (const float*)d_in[4];
    const float* b_ve1 = (const float*)d_in[5];
    const float* W_ve2 = (const float*)d_in[6];
    const float* b_ve2 = (const float*)d_in[7];
    const float* W_ce1 = (const float*)d_in[8];
    const float* b_ce1 = (const float*)d_in[9];
    const float* W_ce2 = (const float*)d_in[10];
    const float* b_ce2 = (const float*)d_in[11];
    const float* W_v2c = (const float*)d_in[12];
    const float* b_v2c = (const float*)d_in[13];
    const float* W_c2v = (const float*)d_in[14];
    const float* b_c2v = (const float*)d_in[15];
    const float* W_ro  = (const float*)d_in[16];
    const float* b_ro  = (const float*)d_in[17];
    float* scores = (float*)d_out;

    float *hvar, *hcon, *tbuf;
    __half* t16;
    int *row_var, *row_con, *adj_var, *adj_con, *deg_var, *deg_con, *bsv, *bsc;
    cudaGetSymbolAddress((void**)&hvar, g_hvar);
    cudaGetSymbolAddress((void**)&hcon, g_hcon);
    cudaGetSymbolAddress((void**)&tbuf, g_t);
    cudaGetSymbolAddress((void**)&t16, g_t16);
    cudaGetSymbolAddress((void**)&row_var, g_row_var);
    cudaGetSymbolAddress((void**)&row_con, g_row_con);
    cudaGetSymbolAddress((void**)&adj_var, g_adj_var);
    cudaGetSymbolAddress((void**)&adj_con, g_adj_con);
    cudaGetSymbolAddress((void**)&deg_var, g_deg_var);
    cudaGetSymbolAddress((void**)&deg_con, g_deg_con);
    cudaGetSymbolAddress((void**)&bsv, g_bsum_var);
    cudaGetSymbolAddress((void**)&bsc, g_bsum_con);

    const int GEMM_SMEM = (2 * 64 * GPAD + 64 * XPAD + 128) * sizeof(float);
    const int ENCV_SMEM = (64 * VFEAT + 64 + 64 * GPAD + 64 * XPAD) * sizeof(float);
    const int ENCC_SMEM = (64 * CFEAT + 64 + 64 * GPAD + 64 * XPAD) * sizeof(float);
    cudaFuncSetAttribute((const void*)k_gemm_pair, cudaFuncAttributeMaxDynamicSharedMemorySize, GEMM_SMEM);
    cudaFuncSetAttribute((const void*)k_enc<VFEAT>, cudaFuncAttributeMaxDynamicSharedMemorySize, ENCV_SMEM);
    cudaFuncSetAttribute((const void*)k_enc<CFEAT>, cudaFuncAttributeMaxDynamicSharedMemorySize, ENCC_SMEM);

    // ---- single side stream ----
    cudaStream_t s2;
    cudaStreamCreateWithFlags(&s2, cudaStreamNonBlocking);
    cudaEvent_t evFork, evEnc, evVar;
    cudaEventCreateWithFlags(&evFork, cudaEventDisableTiming);
    cudaEventCreateWithFlags(&evEnc, cudaEventDisableTiming);
    cudaEventCreateWithFlags(&evVar, cudaEventDisableTiming);
    cudaEventRecord(evFork, 0);
    cudaStreamWaitEvent(s2, evFork, 0);

    // s2: encoders, then var-side CSR chain (deg_var self-restoring; no zeroing)
    k_enc<VFEAT><<<(NV + 127) / 128, 128, ENCV_SMEM, s2>>>(var_features, W_ve1, b_ve1, W_ve2, b_ve2, hvar, NV);
    k_enc<CFEAT><<<(NC + 127) / 128, 128, ENCC_SMEM, s2>>>(con_features, W_ce1, b_ce1, W_ce2, b_ce2, hcon, NC);
    cudaEventRecord(evEnc, s2);
    k_hist1<<<(NE + 255) / 256, 256, 0, s2>>>(edge_var, deg_var);
    k_scan_a<<<NBV_, 256, 0, s2>>>(deg_var, NV, bsv);
    k_scan_b<<<1, 128, 0, s2>>>(bsv, NBV_);
    k_scan_c<<<NBV_, 256, 0, s2>>>(deg_var, row_var, bsv, NV);
    k_fill1<<<(NE + 255) / 256, 256, 0, s2>>>(edge_var, edge_con, row_var, deg_var, adj_var);
    cudaEventRecord(evVar, s2);

    // main: con-side CSR chain (deg_con self-restoring)
    k_hist1<<<(NE + 255) / 256, 256>>>(edge_con, deg_con);
    k_scan_a<<<NBC_, 256>>>(deg_con, NC, bsc);
    k_scan_b<<<1, 128>>>(bsc, NBC_);
    k_scan_c<<<NBC_, 256>>>(deg_con, row_con, bsc, NC);
    k_fill1<<<(NE + 255) / 256, 256>>>(edge_con, edge_var, row_con, deg_con, adj_con);

    // join encoders before round loop
    cudaStreamWaitEvent(0, evEnc, 0);

    // ---- message passing rounds ----
    for (int r = 0; r < NROUNDS; r++) {
        k_agg<<<(NC * 16 + 255) / 256, 256>>>(hvar, row_con, adj_con, tbuf, NC);
        k_gemm_pair<<<(NC + 127) / 128, 128, GEMM_SMEM>>>(tbuf, W_v2c + r * 4096, b_v2c + r * 64,
                                                          row_con, hcon, W_c2v + r * 4096, t16, NC);
        if (r == 0) cudaStreamWaitEvent(0, evVar, 0);   // late join of var CSR chain
        if (r < NROUNDS - 1) {
            k_agg_update<<<(NV * 16 + 255) / 256, 256>>>(t16, row_var, adj_var, hvar,
                                                         b_c2v + r * 64, NV);
        } else {
            k_agg_update_ro<<<(NV * 16 + 255) / 256, 256>>>(t16, row_var, adj_var, hvar,
                                                            b_c2v + r * 64, W_ro, b_ro,
                                                            scores, NV);
        }
    }
}

// round 17
// speedup vs baseline: 1.0474x; 1.0020x over previous
#include <cuda_runtime.h>
#include <cuda_fp16.h>
#include <math.h>
#include <string.h>

#define NV 200000
#define NC 100000
#define NE 1200000
#define VFEAT 7
#define CFEAT 5
#define HDIM 64
#define NROUNDS 2
#define SCAN_TILE 2048
#define NBC_ ((NC + SCAN_TILE - 1) / SCAN_TILE)   // 49
#define NBV_ ((NV + SCAN_TILE - 1) / SCAN_TILE)   // 98
#define GPAD 68
#define XPAD 136

typedef unsigned long long ull;

// ---------------- fast helpers ----------------
__device__ __forceinline__ float fast_tanh(float x) {
    float y;
    asm("tanh.approx.f32 %0, %1;" : "=f"(y) : "f"(x));
    return y;
}
__device__ __forceinline__ ull bcast2(float x) {
    ull r;
    unsigned u = __float_as_uint(x);
    asm("mov.b64 %0, {%1, %1};" : "=l"(r) : "r"(u));
    return r;
}
__device__ __forceinline__ void ffma2(ull& d, ull a, ull b) {
    asm("fma.rn.f32x2 %0, %1, %2, %0;" : "+l"(d) : "l"(a), "l"(b));
}
__device__ __forceinline__ float2 unpack2(ull v) {
    float2 f;
    memcpy(&f, &v, 8);
    return f;
}
__device__ __forceinline__ unsigned packh2(float a, float b) {
    __half2 h = __floats2half2_rn(a, b);
    unsigned u;
    memcpy(&u, &h, 4);
    return u;
}
__device__ __forceinline__ float4 cvt_h4(uint2 u) {
    __half2 h0, h1;
    memcpy(&h0, &u.x, 4);
    memcpy(&h1, &u.y, 4);
    float2 a = __half22float2(h0);
    float2 b = __half22float2(h1);
    return make_float4(a.x, a.y, b.x, b.y);
}

// ---------------- device scratch ----------------
__device__ float  g_hvar[NV * HDIM];
__device__ float  g_hcon[NC * HDIM];
__device__ float  g_t[NV * HDIM];       // fp32 agg buffer (con side)
__device__ __half g_t16[NC * HDIM];     // fp16 messages (var side gathers these)
__device__ int   g_deg_var[NV];         // zero-init; self-restoring (fill consumes to 0)
__device__ int   g_deg_con[NC];         // zero-init; self-restoring
__device__ int   g_row_var[NV + 1];
__device__ int   g_row_con[NC + 1];
__device__ int   g_adj_var[NE];
__device__ int   g_adj_con[NE];
__device__ int   g_bsum_var[128];
__device__ int   g_bsum_con[64];

// ---------------- per-side histogram ----------------
__global__ void k_hist1(const int* __restrict__ idx, int* __restrict__ deg) {
    int e = blockIdx.x * blockDim.x + threadIdx.x;
    if (e < NE) atomicAdd(&deg[idx[e]], 1);
}

// ---------------- scan phase A ----------------
__global__ void k_scan_a(const int* __restrict__ deg, int n, int* __restrict__ bsum) {
    __shared__ int ws[8];
    int idx0 = blockIdx.x * SCAN_TILE + threadIdx.x * 8;
    int local = 0;
    #pragma unroll
    for (int i = 0; i < 8; i++) {
        int id = idx0 + i;
        if (id < n) local += deg[id];
    }
    int lane = threadIdx.x & 31, w = threadIdx.x >> 5;
    #pragma unroll
    for (int o = 16; o; o >>= 1) local += __shfl_xor_sync(0xffffffffu, local, o);
    if (lane == 0) ws[w] = local;
    __syncthreads();
    if (threadIdx.x == 0) {
        int s = 0;
        #pragma unroll
        for (int i = 0; i < 8; i++) s += ws[i];
        bsum[blockIdx.x] = s;
    }
}

// ---------------- scan phase B ----------------
__global__ void k_scan_b(int* bsum, int nb) {
    __shared__ int ws[4];
    int tid = threadIdx.x;
    int v = (tid < nb) ? bsum[tid] : 0;
    int lane = tid & 31, w = tid >> 5;
    int inc = v;
    #pragma unroll
    for (int o = 1; o < 32; o <<= 1) {
        int y = __shfl_up_sync(0xffffffffu, inc, o);
        if (lane >= o) inc += y;
    }
    if (lane == 31) ws[w] = inc;
    __syncthreads();
    int add = 0;
    for (int i = 0; i < w; i++) add += ws[i];
    if (tid < nb) bsum[tid] = inc - v + add;
}

// ---------------- scan phase C ----------------
__global__ void k_scan_c(const int* __restrict__ deg, int* __restrict__ row,
                         const int* __restrict__ bsum, int n) {
    __shared__ int wsum[8];
    int idx0 = blockIdx.x * SCAN_TILE + threadIdx.x * 8;
    int pre[8];
    int local = 0;
    #pragma unroll
    for (int i = 0; i < 8; i++) {
        int id = idx0 + i;
        int x = (id < n) ? deg[id] : 0;
        pre[i] = local;
        local += x;
    }
    int lane = threadIdx.x & 31, w = threadIdx.x >> 5;
    int inc = local;
    #pragma unroll
    for (int o = 1; o < 32; o <<= 1) {
        int y = __shfl_up_sync(0xffffffffu, inc, o);
        if (lane >= o) inc += y;
    }
    if (lane == 31) wsum[w] = inc;
    __syncthreads();
    int add = 0;
    for (int i = 0; i < w; i++) add += wsum[i];
    int texcl = bsum[blockIdx.x] + add + (inc - local);
    #pragma unroll
    for (int i = 0; i < 8; i++) {
        int id = idx0 + i;
        if (id < n) row[id] = texcl + pre[i];
    }
    if (blockIdx.x == 0 && threadIdx.x == 0) row[n] = NE;
}

// ---------------- per-side CSR fill (consumes deg via atomicSub -> leaves deg at 0) ----------------
__global__ void k_fill1(const int* __restrict__ key, const int* __restrict__ val,
                        const int* __restrict__ rowp, int* __restrict__ deg,
                        int* __restrict__ adj) {
    int e = blockIdx.x * blockDim.x + threadIdx.x;
    if (e < NE) {
        int k = key[e];
        int p = rowp[k] + (atomicSub(&deg[k], 1) - 1);
        adj[p] = val[e];
    }
}

// ---------------- 8x8-tile 64x64 GEMM core ----------------
__device__ __forceinline__ void gemm64_8x8(
    const float* Wt, const float* Xt, int j0, int n0, ull acc[8][4]) {
    #pragma unroll
    for (int a = 0; a < 8; a++) { acc[a][0] = 0ull; acc[a][1] = 0ull; acc[a][2] = 0ull; acc[a][3] = 0ull; }
    #pragma unroll 8
    for (int k = 0; k < 64; k++) {
        const float* wr = Wt + k * GPAD + j0;
        ulonglong2 wa = *(const ulonglong2*)wr;
        ulonglong2 wb = *(const ulonglong2*)(wr + 4);
        const float* xr = Xt + k * XPAD + n0;
        float4 xa = *(const float4*)xr;
        float4 xb = *(const float4*)(xr + 4);
        float xs[8] = {xa.x, xa.y, xa.z, xa.w, xb.x, xb.y, xb.z, xb.w};
        #pragma unroll
        for (int ni = 0; ni < 8; ni++) {
            ull xp = bcast2(xs[ni]);
            ffma2(acc[ni][0], xp, wa.x);
            ffma2(acc[ni][1], xp, wa.y);
            ffma2(acc[ni][2], xp, wb.x);
            ffma2(acc[ni][3], xp, wb.y);
        }
    }
}

// ---------------- fused encoder ----------------
template <int F>
__global__ __launch_bounds__(128) void k_enc(
    const float* __restrict__ x, const float* __restrict__ W1,
    const float* __restrict__ b1, const float* __restrict__ W2,
    const float* __restrict__ b2, float* __restrict__ out, int n) {
    extern __shared__ float sm[];
    float* W1s = sm;
    float* b1s = sm + 64 * F;
    float* W2t = sm + 64 * F + 64;
    float* Xt  = sm + 64 * F + 64 + 64 * GPAD;
    int tid = threadIdx.x;
    int row0 = blockIdx.x * 128;
    for (int i = tid; i < 64 * F; i += 128) W1s[i] = W1[i];
    if (tid < 64) b1s[tid] = b1[tid];
    #pragma unroll
    for (int i = tid; i < 4096; i += 128) {
        int j = i >> 6, k = i & 63;
        W2t[k * GPAD + j] = W2[i];
    }
    float xf[F];
    {
        int row = row0 + tid;
        if (row < n) {
            #pragma unroll
            for (int f = 0; f < F; f++) xf[f] = x[(size_t)row * F + f];
        } else {
            #pragma unroll
            for (int f = 0; f < F; f++) xf[f] = 0.f;
        }
    }
    __syncthreads();
    {
        int row = row0 + tid;
        if (row < n) {
            #pragma unroll 4
            for (int k = 0; k < 64; k++) {
                float a = b1s[k];
                #pragma unroll
                for (int f = 0; f < F; f++) a += xf[f] * W1s[k * F + f];
                Xt[k * XPAD + tid] = fast_tanh(a);
            }
        } else {
            #pragma unroll 8
            for (int k = 0; k < 64; k++) Xt[k * XPAD + tid] = 0.f;
        }
    }
    __syncthreads();
    const int j0 = (tid & 7) * 8;
    const int n0 = (tid >> 3) * 8;
    ull acc[8][4];
    gemm64_8x8(W2t, Xt, j0, n0, acc);
    float4 ba = *(const float4*)&b2[j0];
    float4 bb = *(const float4*)&b2[j0 + 4];
    #pragma unroll
    for (int ni = 0; ni < 8; ni++) {
        int row = row0 + n0 + ni;
        if (row >= n) break;
        float2 p0 = unpack2(acc[ni][0]), p1 = unpack2(acc[ni][1]);
        float2 p2 = unpack2(acc[ni][2]), p3 = unpack2(acc[ni][3]);
        *(float4*)&out[(size_t)row * 64 + j0]     = make_float4(p0.x + ba.x, p0.y + ba.y, p1.x + ba.z, p1.y + ba.w);
        *(float4*)&out[(size_t)row * 64 + j0 + 4] = make_float4(p2.x + bb.x, p2.y + bb.y, p3.x + bb.z, p3.y + bb.w);
    }
}

// ---------------- fused round GEMM pair (dual weight buffers; fp16 msg out) ----------------
__global__ __launch_bounds__(128) void k_gemm_pair(
    const float* __restrict__ agg, const float* __restrict__ W1,
    const float* __restrict__ b1, const int* __restrict__ rowp,
    float* hcon, const float* __restrict__ W2, __half* __restrict__ tout16, int n) {
    extern __shared__ float sm[];
    float* W1t  = sm;
    float* W2t  = sm + 64 * GPAD;
    float* Xt   = sm + 2 * 64 * GPAD;
    float* degs = sm + 2 * 64 * GPAD + 64 * XPAD;
    int tid = threadIdx.x;
    int row0 = blockIdx.x * 128;
    #pragma unroll
    for (int i = tid; i < 4096; i += 128) {
        int j = i >> 6, k = i & 63;
        W1t[k * GPAD + j] = W1[i];
        W2t[k * GPAD + j] = W2[i];
    }
    {
        int r = tid, row = row0 + r;
        if (row < n) {
            const float4* s4 = (const float4*)(agg + (size_t)row * 64);
            #pragma unroll
            for (int kk = 0; kk < 16; kk++) {
                float4 v = s4[kk];
                Xt[(kk * 4 + 0) * XPAD + r] = v.x;
                Xt[(kk * 4 + 1) * XPAD + r] = v.y;
                Xt[(kk * 4 + 2) * XPAD + r] = v.z;
                Xt[(kk * 4 + 3) * XPAD + r] = v.w;
            }
            degs[r] = (float)(rowp[row + 1] - rowp[row]);
        } else {
            #pragma unroll 8
            for (int k = 0; k < 64; k++) Xt[k * XPAD + r] = 0.f;
            degs[r] = 0.f;
        }
    }
    __syncthreads();
    const int j0 = (tid & 7) * 8;
    const int n0 = (tid >> 3) * 8;
    ull acc[8][4];
    gemm64_8x8(W1t, Xt, j0, n0, acc);
    __syncthreads();
    float4 ba = *(const float4*)&b1[j0];
    float4 bb = *(const float4*)&b1[j0 + 4];
    #pragma unroll
    for (int ni = 0; ni < 8; ni++) {
        int row = row0 + n0 + ni;
        float h[8];
        float2 p0 = unpack2(acc[ni][0]), p1 = unpack2(acc[ni][1]);
        float2 p2 = unpack2(acc[ni][2]), p3 = unpack2(acc[ni][3]);
        h[0] = p0.x; h[1] = p0.y; h[2] = p1.x; h[3] = p1.y;
        h[4] = p2.x; h[5] = p2.y; h[6] = p3.x; h[7] = p3.y;
        if (row < n) {
            float s = degs[n0 + ni];
            float4 r0 = *(const float4*)&hcon[(size_t)row * 64 + j0];
            float4 r1 = *(const float4*)&hcon[(size_t)row * 64 + j0 + 4];
            h[0] = fast_tanh(h[0] + ba.x * s + r0.x);
            h[1] = fast_tanh(h[1] + ba.y * s + r0.y);
            h[2] = fast_tanh(h[2] + ba.z * s + r0.z);
            h[3] = fast_tanh(h[3] + ba.w * s + r0.w);
            h[4] = fast_tanh(h[4] + bb.x * s + r1.x);
            h[5] = fast_tanh(h[5] + bb.y * s + r1.y);
            h[6] = fast_tanh(h[6] + bb.z * s + r1.z);
            h[7] = fast_tanh(h[7] + bb.w * s + r1.w);
            *(float4*)&hcon[(size_t)row * 64 + j0]     = make_float4(h[0], h[1], h[2], h[3]);
            *(float4*)&hcon[(size_t)row * 64 + j0 + 4] = make_float4(h[4], h[5], h[6], h[7]);
        } else {
            #pragma unroll
            for (int jj = 0; jj < 8; jj++) h[jj] = 0.f;
        }
        #pragma unroll
        for (int jj = 0; jj < 8; jj++) Xt[(j0 + jj) * XPAD + n0 + ni] = h[jj];
    }
    __syncthreads();
    gemm64_8x8(W2t, Xt, j0, n0, acc);
    #pragma unroll
    for (int ni = 0; ni < 8; ni++) {
        int row = row0 + n0 + ni;
        if (row >= n) break;
        float2 p0 = unpack2(acc[ni][0]), p1 = unpack2(acc[ni][1]);
        float2 p2 = unpack2(acc[ni][2]), p3 = unpack2(acc[ni][3]);
        uint4 v;
        v.x = packh2(p0.x, p0.y);
        v.y = packh2(p1.x, p1.y);
        v.z = packh2(p2.x, p2.y);
        v.w = packh2(p3.x, p3.y);
        *(uint4*)&tout16[(size_t)row * 64 + j0] = v;
    }
}

// ---------------- half-warp-per-row gather core (fp32 src, paired tail) ----------------
__device__ __forceinline__ float4 gather_row_hw(
    const float* __restrict__ src, const int* __restrict__ adj,
    int b, int e, int fl) {
    float4 a0 = make_float4(0.f, 0.f, 0.f, 0.f);
    float4 a1 = a0, a2 = a0, a3 = a0;
    int i = b;
    for (; i + 4 <= e; i += 4) {
        int v0 = adj[i], v1 = adj[i + 1], v2 = adj[i + 2], v3 = adj[i + 3];
        float4 x0 = *(const float4*)&src[(size_t)v0 * 64 + fl * 4];
        float4 x1 = *(const float4*)&src[(size_t)v1 * 64 + fl * 4];
        float4 x2 = *(const float4*)&src[(size_t)v2 * 64 + fl * 4];
        float4 x3 = *(const float4*)&src[(size_t)v3 * 64 + fl * 4];
        a0.x += x0.x; a0.y += x0.y; a0.z += x0.z; a0.w += x0.w;
        a1.x += x1.x; a1.y += x1.y; a1.z += x1.z; a1.w += x1.w;
        a2.x += x2.x; a2.y += x2.y; a2.z += x2.z; a2.w += x2.w;
        a3.x += x3.x; a3.y += x3.y; a3.z += x3.z; a3.w += x3.w;
    }
    if (i + 2 <= e) {
        int v0 = adj[i], v1 = adj[i + 1];
        float4 x0 = *(const float4*)&src[(size_t)v0 * 64 + fl * 4];
        float4 x1 = *(const float4*)&src[(size_t)v1 * 64 + fl * 4];
        a0.x += x0.x; a0.y += x0.y; a0.z += x0.z; a0.w += x0.w;
        a1.x += x1.x; a1.y += x1.y; a1.z += x1.z; a1.w += x1.w;
        i += 2;
    }
    if (i < e) {
        int v = adj[i];
        float4 x = *(const float4*)&src[(size_t)v * 64 + fl * 4];
        a0.x += x.x; a0.y += x.y; a0.z += x.z; a0.w += x.w;
    }
    a0.x = (a0.x + a1.x) + (a2.x + a3.x);
    a0.y = (a0.y + a1.y) + (a2.y + a3.y);
    a0.z = (a0.z + a1.z) + (a2.z + a3.z);
    a0.w = (a0.w + a1.w) + (a2.w + a3.w);
    return a0;
}

// ---------------- half-warp-per-row gather core (fp16 src, fp32 accum, paired tail) ----------------
__device__ __forceinline__ float4 gather_row_hw_h(
    const __half* __restrict__ src, const int* __restrict__ adj,
    int b, int e, int fl) {
    float4 a0 = make_float4(0.f, 0.f, 0.f, 0.f);
    float4 a1 = a0, a2 = a0, a3 = a0;
    int i = b;
    for (; i + 4 <= e; i += 4) {
        int v0 = adj[i], v1 = adj[i + 1], v2 = adj[i + 2], v3 = adj[i + 3];
        uint2 u0 = *(const uint2*)&src[(size_t)v0 * 64 + fl * 4];
        uint2 u1 = *(const uint2*)&src[(size_t)v1 * 64 + fl * 4];
        uint2 u2 = *(const uint2*)&src[(size_t)v2 * 64 + fl * 4];
        uint2 u3 = *(const uint2*)&src[(size_t)v3 * 64 + fl * 4];
        float4 x0 = cvt_h4(u0), x1 = cvt_h4(u1), x2 = cvt_h4(u2), x3 = cvt_h4(u3);
        a0.x += x0.x; a0.y += x0.y; a0.z += x0.z; a0.w += x0.w;
        a1.x += x1.x; a1.y += x1.y; a1.z += x1.z; a1.w += x1.w;
        a2.x += x2.x; a2.y += x2.y; a2.z += x2.z; a2.w += x2.w;
        a3.x += x3.x; a3.y += x3.y; a3.z += x3.z; a3.w += x3.w;
    }
    if (i + 2 <= e) {
        int v0 = adj[i], v1 = adj[i + 1];
        uint2 u0 = *(const uint2*)&src[(size_t)v0 * 64 + fl * 4];
        uint2 u1 = *(const uint2*)&src[(size_t)v1 * 64 + fl * 4];
        float4 x0 = cvt_h4(u0), x1 = cvt_h4(u1);
        a0.x += x0.x; a0.y += x0.y; a0.z += x0.z; a0.w += x0.w;
        a1.x += x1.x; a1.y += x1.y; a1.z += x1.z; a1.w += x1.w;
        i += 2;
    }
    if (i < e) {
        int v = adj[i];
        uint2 u = *(const uint2*)&src[(size_t)v * 64 + fl * 4];
        float4 x = cvt_h4(u);
        a0.x += x.x; a0.y += x.y; a0.z += x.z; a0.w += x.w;
    }
    a0.x = (a0.x + a1.x) + (a2.x + a3.x);
    a0.y = (a0.y + a1.y) + (a2.y + a3.y);
    a0.z = (a0.z + a1.z) + (a2.z + a3.z);
    a0.w = (a0.w + a1.w) + (a2.w + a3.w);
    return a0;
}

// ---------------- gather aggregation (2 rows per warp, fp32 src) ----------------
__global__ __launch_bounds__(256) void k_agg(
    const float* __restrict__ src, const int* __restrict__ rowp,
    const int* __restrict__ adj, float* __restrict__ out, int n) {
    int gw = (blockIdx.x * 256 + threadIdx.x) >> 5;
    int lane = threadIdx.x & 31;
    int half = lane >> 4, fl = lane & 15;
    int row = gw * 2 + half;
    if (gw * 2 >= n) return;
    int b = rowp[row], e = rowp[row + 1];
    float4 a = gather_row_hw(src, adj, b, e, fl);
    *(float4*)&out[(size_t)row * 64 + fl * 4] = a;
}

// ---------------- gather + update (2 rows per warp, fp16 src) ----------------
__global__ __launch_bounds__(256) void k_agg_update(
    const __half* __restrict__ src16, const int* __restrict__ rowp,
    const int* __restrict__ adj, float* h, const float* __restrict__ bias, int n) {
    int gw = (blockIdx.x * 256 + threadIdx.x) >> 5;
    int lane = threadIdx.x & 31;
    int half = lane >> 4, fl = lane & 15;
    int row = gw * 2 + half;
    if (gw * 2 >= n) return;
    int b = rowp[row], e = rowp[row + 1];
    float4 a = gather_row_hw_h(src16, adj, b, e, fl);
    float d = (float)(e - b);
    float4 bb = *(const float4*)&bias[fl * 4];
    float4 hv = *(const float4*)&h[(size_t)row * 64 + fl * 4];
    hv.x = fast_tanh(hv.x + a.x + d * bb.x);
    hv.y = fast_tanh(hv.y + a.y + d * bb.y);
    hv.z = fast_tanh(hv.z + a.z + d * bb.z);
    hv.w = fast_tanh(hv.w + a.w + d * bb.w);
    *(float4*)&h[(size_t)row * 64 + fl * 4] = hv;
}

// ---------------- final: gather + update + readout (2 rows per warp, fp16 src) ----------------
__global__ __launch_bounds__(256) void k_agg_update_ro(
    const __half* __restrict__ src16, const int* __restrict__ rowp,
    const int* __restrict__ adj, const float* __restrict__ h,
    const float* __restrict__ bias, const float* __restrict__ Wro,
    const float* __restrict__ bro, float* __restrict__ scores, int n) {
    int gw = (blockIdx.x * 256 + threadIdx.x) >> 5;
    int lane = threadIdx.x & 31;
    int half = lane >> 4, fl = lane & 15;
    int row = gw * 2 + half;
    if (gw * 2 >= n) return;
    int b = rowp[row], e = rowp[row + 1];
    float4 a = gather_row_hw_h(src16, adj, b, e, fl);
    float d = (float)(e - b);
    float4 bb = *(const float4*)&bias[fl * 4];
    float4 hv = *(const float4*)&h[(size_t)row * 64 + fl * 4];
    float4 ww = *(const float4*)&Wro[fl * 4];
    float hx = fast_tanh(hv.x + a.x + d * bb.x);
    float hy = fast_tanh(hv.y + a.y + d * bb.y);
    float hz = fast_tanh(hv.z + a.z + d * bb.z);
    float hw = fast_tanh(hv.w + a.w + d * bb.w);
    float s = hx * ww.x + hy * ww.y + hz * ww.z + hw * ww.w;
    #pragma unroll
    for (int o = 8; o; o >>= 1) s += __shfl_xor_sync(0xffffffffu, s, o);
    if (fl == 0) scores[row] = s + bro[0];
}

// ---------------- launch ----------------
extern "C" void kernel_launch(void* const* d_in, const int* in_sizes, int n_in,
                              void* d_out, int out_size) {
    const float* var_features = (const float*)d_in[0];
    const float* con_features = (const float*)d_in[1];
    const int*   edge_var     = (const int*)d_in[2];
    const int*   edge_con     = (const int*)d_in[3];
    const float* W_ve1 = (const float*)d_in[4];
    const float* b_ve1 = (const float*)d_in[5];
    const float* W_ve2 = (const float*)d_in[6];
    const float* b_ve2 = (const float*)d_in[7];
    const float* W_ce1 = (const float*)d_in[8];
    const float* b_ce1 = (const float*)d_in[9];
    const float* W_ce2 = (const float*)d_in[10];
    const float* b_ce2 = (const float*)d_in[11];
    const float* W_v2c = (const float*)d_in[12];
    const float* b_v2c = (const float*)d_in[13];
    const float* W_c2v = (const float*)d_in[14];
    const float* b_c2v = (const float*)d_in[15];
    const float* W_ro  = (const float*)d_in[16];
    const float* b_ro  = (const float*)d_in[17];
    float* scores = (float*)d_out;

    float *hvar, *hcon, *tbuf;
    __half* t16;
    int *row_var, *row_con, *adj_var, *adj_con, *deg_var, *deg_con, *bsv, *bsc;
    cudaGetSymbolAddress((void**)&hvar, g_hvar);
    cudaGetSymbolAddress((void**)&hcon, g_hcon);
    cudaGetSymbolAddress((void**)&tbuf, g_t);
    cudaGetSymbolAddress((void**)&t16, g_t16);
    cudaGetSymbolAddress((void**)&row_var, g_row_var);
    cudaGetSymbolAddress((void**)&row_con, g_row_con);
    cudaGetSymbolAddress((void**)&adj_var, g_adj_var);
    cudaGetSymbolAddress((void**)&adj_con, g_adj_con);
    cudaGetSymbolAddress((void**)&deg_var, g_deg_var);
    cudaGetSymbolAddress((void**)&deg_con, g_deg_con);
    cudaGetSymbolAddress((void**)&bsv, g_bsum_var);
    cudaGetSymbolAddress((void**)&bsc, g_bsum_con);

    const int GEMM_SMEM = (2 * 64 * GPAD + 64 * XPAD + 128) * sizeof(float);
    const int ENCV_SMEM = (64 * VFEAT + 64 + 64 * GPAD + 64 * XPAD) * sizeof(float);
    const int ENCC_SMEM = (64 * CFEAT + 64 + 64 * GPAD + 64 * XPAD) * sizeof(float);
    cudaFuncSetAttribute((const void*)k_gemm_pair, cudaFuncAttributeMaxDynamicSharedMemorySize, GEMM_SMEM);
    cudaFuncSetAttribute((const void*)k_enc<VFEAT>, cudaFuncAttributeMaxDynamicSharedMemorySize, ENCV_SMEM);
    cudaFuncSetAttribute((const void*)k_enc<CFEAT>, cudaFuncAttributeMaxDynamicSharedMemorySize, ENCC_SMEM);

    // ---- single side stream ----
    cudaStream_t s2;
    cudaStreamCreateWithFlags(&s2, cudaStreamNonBlocking);
    cudaEvent_t evFork, evEnc, evVar;
    cudaEventCreateWithFlags(&evFork, cudaEventDisableTiming);
    cudaEventCreateWithFlags(&evEnc, cudaEventDisableTiming);
    cudaEventCreateWithFlags(&evVar, cudaEventDisableTiming);
    cudaEventRecord(evFork, 0);
    cudaStreamWaitEvent(s2, evFork, 0);

    // s2: encoders, then var-side CSR chain (deg_var self-restoring; no zeroing)
    k_enc<VFEAT><<<(NV + 127) / 128, 128, ENCV_SMEM, s2>>>(var_features, W_ve1, b_ve1, W_ve2, b_ve2, hvar, NV);
    k_enc<CFEAT><<<(NC + 127) / 128, 128, ENCC_SMEM, s2>>>(con_features, W_ce1, b_ce1, W_ce2, b_ce2, hcon, NC);
    cudaEventRecord(evEnc, s2);
    k_hist1<<<(NE + 255) / 256, 256, 0, s2>>>(edge_var, deg_var);
    k_scan_a<<<NBV_, 256, 0, s2>>>(deg_var, NV, bsv);
    k_scan_b<<<1, 128, 0, s2>>>(bsv, NBV_);
    k_scan_c<<<NBV_, 256, 0, s2>>>(deg_var, row_var, bsv, NV);
    k_fill1<<<(NE + 255) / 256, 256, 0, s2>>>(edge_var, edge_con, row_var, deg_var, adj_var);
    cudaEventRecord(evVar, s2);

    // main: con-side CSR chain (deg_con self-restoring)
    k_hist1<<<(NE + 255) / 256, 256>>>(edge_con, deg_con);
    k_scan_a<<<NBC_, 256>>>(deg_con, NC, bsc);
    k_scan_b<<<1, 128>>>(bsc, NBC_);
    k_scan_c<<<NBC_, 256>>>(deg_con, row_con, bsc, NC);
    k_fill1<<<(NE + 255) / 256, 256>>>(edge_con, edge_var, row_con, deg_con, adj_con);

    // join encoders before round loop
    cudaStreamWaitEvent(0, evEnc, 0);

    // ---- message passing rounds ----
    for (int r = 0; r < NROUNDS; r++) {
        k_agg<<<(NC * 16 + 255) / 256, 256>>>(hvar, row_con, adj_con, tbuf, NC);
        k_gemm_pair<<<(NC + 127) / 128, 128, GEMM_SMEM>>>(tbuf, W_v2c + r * 4096, b_v2c + r * 64,
                                                          row_con, hcon, W_c2v + r * 4096, t16, NC);
        if (r == 0) cudaStreamWaitEvent(0, evVar, 0);   // late join of var CSR chain
        if (r < NROUNDS - 1) {
            k_agg_update<<<(NV * 16 + 255) / 256, 256>>>(t16, row_var, adj_var, hvar,
                                                         b_c2v + r * 64, NV);
        } else {
            k_agg_update_ro<<<(NV * 16 + 255) / 256, 256>>>(t16, row_var, adj_var, hvar,
                                                            b_c2v + r * 64, W_ro, b_ro,
                                                            scores, NV);
        }
    }
}